// round 4
// baseline (speedup 1.0000x reference)
#include <cuda_runtime.h>
#include <math.h>
#include <stdint.h>

#define BSZ  64
#define LEN  256
#define DM   512
#define DFF  2048
#define NEXP 992
#define M1   (BSZ * LEN)            // 16384
#define NSPLIT 8
#define ZSCALE 0.044194173824159216f   // 1/sqrt(512)

// dense GEMM tiling
#define GBM 128
#define GBN 128
#define GBK 16
#define AST 20    // As row stride (floats): 16 + 4 pad
#define BST 132   // Bs row stride (floats): 128 + 4 pad

// class GEMM tiling (128x64 tile, dual accumulators)
#define ASTC 17   // 16 + 1 pad
#define BSTC 68   // 64 + 4 pad
#define CSTAGE (128 * ASTC * 2 + 16 * BSTC * 2)   // floats per stage = 6528
#define CSMEM  (CSTAGE * 2 * 4)                   // bytes = 52224

// ------------------------- scratch (static device globals) -------------------------
static __device__ float g_X2  [(size_t)M1 * DM];
static __device__ float g_XK  [(size_t)M1 * DM];
static __device__ float g_EA0 [(size_t)M1 * DM];
static __device__ float g_EB0 [(size_t)M1 * DM];
static __device__ float g_AE  [(size_t)M1 * DM];
static __device__ float g_BE  [(size_t)M1 * DM];
static __device__ float g_SEL [(size_t)M1 * DM];
static __device__ float g_X1  [(size_t)M1 * DM];
static __device__ float g_Z   [(size_t)BSZ * NEXP * LEN];
static __device__ float g_CA  [(size_t)BSZ * NEXP * DM];
static __device__ float g_CB  [(size_t)BSZ * NEXP * DM];
static __device__ float g_H   [(size_t)M1 * DFF];
static __device__ float g_IAf [BSZ * NEXP];
static __device__ float g_IBf [BSZ * NEXP];
static __device__ float g_PA  [BSZ * NSPLIT * LEN];
static __device__ float g_PB  [BSZ * NSPLIT * LEN];
static __device__ float g_IAb [BSZ * LEN];
static __device__ float g_IBb [BSZ * LEN];
static __device__ float g_WR  [3670016];           // rounded weights
static __device__ float g_QR  [(size_t)NEXP * DM]; // rounded q_tab

// ------------------------- helpers -------------------------
__device__ __forceinline__ float rna(float x) {
    uint32_t u;
    asm("cvt.rna.tf32.f32 %0, %1;" : "=r"(u) : "f"(x));
    return __uint_as_float(u);
}

__device__ __forceinline__ void mma8(float* d, const uint32_t* a, const uint32_t* b) {
    asm volatile(
        "mma.sync.aligned.m16n8k8.row.col.f32.tf32.tf32.f32 "
        "{%0,%1,%2,%3}, {%4,%5,%6,%7}, {%8,%9}, {%0,%1,%2,%3};"
        : "+f"(d[0]), "+f"(d[1]), "+f"(d[2]), "+f"(d[3])
        : "r"(a[0]), "r"(a[1]), "r"(a[2]), "r"(a[3]), "r"(b[0]), "r"(b[1]));
}

// round-to-tf32 elementwise pass (float4 granularity)
__global__ void rnd_kernel(const float* __restrict__ s, float* __restrict__ d, int n4)
{
    int i = blockIdx.x * blockDim.x + threadIdx.x;
    if (i < n4) {
        float4 v = reinterpret_cast<const float4*>(s)[i];
        v.x = rna(v.x); v.y = rna(v.y); v.z = rna(v.z); v.w = rna(v.w);
        reinterpret_cast<float4*>(d)[i] = v;
    }
}

// ------------------------- LayerNorm (optionally tf32-rounded output) -------------------------
template <bool RND>
__global__ void ln_kernel(const float* __restrict__ X, const float* __restrict__ G,
                          const float* __restrict__ B, float* __restrict__ O)
{
    __shared__ float sred[4];
    int row = blockIdx.x;
    int t = threadIdx.x;                       // 128 threads, 4 floats each
    const float4 v = reinterpret_cast<const float4*>(X + (size_t)row * DM)[t];
    float s = v.x + v.y + v.z + v.w;
    #pragma unroll
    for (int o = 16; o; o >>= 1) s += __shfl_down_sync(0xffffffffu, s, o);
    if ((t & 31) == 0) sred[t >> 5] = s;
    __syncthreads();
    float mu = (sred[0] + sred[1] + sred[2] + sred[3]) * (1.0f / DM);
    __syncthreads();
    float4 d;
    d.x = v.x - mu; d.y = v.y - mu; d.z = v.z - mu; d.w = v.w - mu;
    float ss = d.x * d.x + d.y * d.y + d.z * d.z + d.w * d.w;
    #pragma unroll
    for (int o = 16; o; o >>= 1) ss += __shfl_down_sync(0xffffffffu, ss, o);
    if ((t & 31) == 0) sred[t >> 5] = ss;
    __syncthreads();
    float var = (sred[0] + sred[1] + sred[2] + sred[3]) * (1.0f / DM);
    float rstd = rsqrtf(var + 1e-5f);
    const float4 g4 = reinterpret_cast<const float4*>(G)[t];
    const float4 b4 = reinterpret_cast<const float4*>(B)[t];
    float4 o4;
    o4.x = d.x * rstd * g4.x + b4.x;
    o4.y = d.y * rstd * g4.y + b4.y;
    o4.z = d.z * rstd * g4.z + b4.z;
    o4.w = d.w * rstd * g4.w + b4.w;
    if (RND) { o4.x = rna(o4.x); o4.y = rna(o4.y); o4.z = rna(o4.z); o4.w = rna(o4.w); }
    reinterpret_cast<float4*>(O + (size_t)row * DM)[t] = o4;
}

// ------------------------- tf32 tensor-core NN GEMM (128x128x16, reg-staged, 1 sync/iter) -----
template <int MODE, bool RND>
__global__ void __launch_bounds__(256) gemm_tf32(
    const float* __restrict__ A, const float* __restrict__ B,
    const float* __restrict__ bias, const float* __restrict__ Dm,
    float* __restrict__ C, int M, int N, int K)
{
    __shared__ float As[2][GBM * AST];
    __shared__ float Bs[2][GBK * BST];
    int tid = threadIdx.x;
    int bm = blockIdx.y * GBM, bn = blockIdx.x * GBN;
    int warp = tid >> 5, lane = tid & 31;
    int wr = warp >> 1, wc = warp & 1;
    int g = lane >> 2, t4 = lane & 3;

    int ar = tid >> 2, ac = (tid & 3) << 2;        // A: 64 rows/half, 4-float cols
    int brr = tid >> 5, bcc = (tid & 31) << 2;     // B: 8 rows/half, 128 cols

    float acc[2][8][4];
    #pragma unroll
    for (int c = 0; c < 2; c++)
        #pragma unroll
        for (int nb = 0; nb < 8; nb++)
            #pragma unroll
            for (int i = 0; i < 4; i++) acc[c][nb][i] = 0.f;

    int KT = K / GBK;
    float4 ra[2], rb[2];

    auto loadregs = [&](int k0) {
        #pragma unroll
        for (int h = 0; h < 2; h++) {
            ra[h] = *reinterpret_cast<const float4*>(A + (size_t)(bm + ar + h * 64) * K + k0 + ac);
            rb[h] = *reinterpret_cast<const float4*>(B + (size_t)(k0 + brr + h * 8) * N + bn + bcc);
        }
    };
    auto storeregs = [&](int s) {
        #pragma unroll
        for (int h = 0; h < 2; h++) {
            *reinterpret_cast<float4*>(&As[s][(ar + h * 64) * AST + ac]) = ra[h];
            *reinterpret_cast<float4*>(&Bs[s][(brr + h * 8) * BST + bcc]) = rb[h];
        }
    };
    auto compute = [&](int s) {
        #pragma unroll
        for (int kk = 0; kk < GBK; kk += 8) {
            uint32_t a[2][4], b[8][2];
            #pragma unroll
            for (int c = 0; c < 2; c++) {
                const float* ap = &As[s][(wr * 32 + c * 16 + g) * AST + kk + t4];
                a[c][0] = __float_as_uint(ap[0]);
                a[c][1] = __float_as_uint(ap[8 * AST]);
                a[c][2] = __float_as_uint(ap[4]);
                a[c][3] = __float_as_uint(ap[8 * AST + 4]);
            }
            #pragma unroll
            for (int nb = 0; nb < 8; nb++) {
                const float* bp = &Bs[s][(kk + t4) * BST + wc * 64 + nb * 8 + g];
                b[nb][0] = __float_as_uint(bp[0]);
                b[nb][1] = __float_as_uint(bp[4 * BST]);
            }
            #pragma unroll
            for (int c = 0; c < 2; c++)
                #pragma unroll
                for (int nb = 0; nb < 8; nb++)
                    mma8(acc[c][nb], a[c], b[nb]);
        }
    };

    loadregs(0);
    storeregs(0);
    __syncthreads();
    for (int t = 0; t < KT; t++) {
        if (t + 1 < KT) loadregs((t + 1) * GBK);
        compute(t & 1);
        if (t + 1 < KT) storeregs((t + 1) & 1);
        __syncthreads();
    }

    #pragma unroll
    for (int c = 0; c < 2; c++) {
        #pragma unroll
        for (int nb = 0; nb < 8; nb++) {
            int n = bn + wc * 64 + nb * 8 + 2 * t4;
            float2 bi = *reinterpret_cast<const float2*>(bias + n);
            #pragma unroll
            for (int h = 0; h < 2; h++) {
                int m = bm + wr * 32 + c * 16 + g + h * 8;
                size_t off = (size_t)m * N + n;
                float v0 = acc[c][nb][h * 2 + 0] + bi.x;
                float v1 = acc[c][nb][h * 2 + 1] + bi.y;
                float2 o;
                if (MODE == 0) {
                    o.x = v0; o.y = v1;
                } else if (MODE == 1) {
                    o.x = 1.f / (1.f + expf(-v0)); o.y = 1.f / (1.f + expf(-v1));
                } else if (MODE == 2) {
                    o.x = fmaxf(v0, 0.f); o.y = fmaxf(v1, 0.f);
                } else if (MODE == 3) {
                    float2 d2 = *reinterpret_cast<const float2*>(Dm + off);
                    o.x = d2.x / (1.f + expf(-v0)); o.y = d2.y / (1.f + expf(-v1));
                } else { // MODE 4
                    float2 d2 = *reinterpret_cast<const float2*>(Dm + off);
                    o.x = d2.x + v0; o.y = d2.y + v1;
                }
                if (RND) { o.x = rna(o.x); o.y = rna(o.y); }
                *reinterpret_cast<float2*>(C + off) = o;
            }
        }
    }
}

// ------------------------- z = gather(q_tab) @ XK^T * scale (reg-staged, 1 sync/iter) ---------
__global__ void __launch_bounds__(256) zgemm_tf32(
    const int* __restrict__ nidx, const float* __restrict__ qr,
    const float* __restrict__ XK, float* __restrict__ Z)
{
    __shared__ float As[2][GBM * AST];
    __shared__ float Bs[2][GBK * BST];
    __shared__ int sidx[GBM];
    int tid = threadIdx.x;
    int b  = blockIdx.z;
    int bm = blockIdx.y * GBM;   // n (expert)
    int bl = blockIdx.x * GBN;   // l
    int warp = tid >> 5, lane = tid & 31;
    int wr = warp >> 1, wc = warp & 1;
    int g = lane >> 2, t4 = lane & 3;

    if (tid < GBM) {
        int n = bm + tid;
        sidx[tid] = nidx[b * NEXP + (n < NEXP ? n : NEXP - 1)];
    }
    __syncthreads();

    float acc[2][8][4];
    #pragma unroll
    for (int c = 0; c < 2; c++)
        #pragma unroll
        for (int nb = 0; nb < 8; nb++)
            #pragma unroll
            for (int i = 0; i < 4; i++) acc[c][nb][i] = 0.f;

    int ar = tid >> 2, ac = (tid & 3) << 2;
    float4 ra[2], rb[2];
    auto loadregs = [&](int k0) {
        #pragma unroll
        for (int h = 0; h < 2; h++) {
            int r = ar + h * 64;
            ra[h] = *reinterpret_cast<const float4*>(qr + (size_t)sidx[r] * DM + k0 + ac);
            rb[h] = *reinterpret_cast<const float4*>(XK + (size_t)(b * LEN + bl + r) * DM + k0 + ac);
        }
    };
    auto storeregs = [&](int s) {
        #pragma unroll
        for (int h = 0; h < 2; h++) {
            int r = ar + h * 64;
            *reinterpret_cast<float4*>(&As[s][r * AST + ac]) = ra[h];
            Bs[s][(ac + 0) * BST + r] = rb[h].x;
            Bs[s][(ac + 1) * BST + r] = rb[h].y;
            Bs[s][(ac + 2) * BST + r] = rb[h].z;
            Bs[s][(ac + 3) * BST + r] = rb[h].w;
        }
    };
    auto compute = [&](int s) {
        #pragma unroll
        for (int kk = 0; kk < GBK; kk += 8) {
            uint32_t a[2][4], bfr[8][2];
            #pragma unroll
            for (int c = 0; c < 2; c++) {
                const float* ap = &As[s][(wr * 32 + c * 16 + g) * AST + kk + t4];
                a[c][0] = __float_as_uint(ap[0]);
                a[c][1] = __float_as_uint(ap[8 * AST]);
                a[c][2] = __float_as_uint(ap[4]);
                a[c][3] = __float_as_uint(ap[8 * AST + 4]);
            }
            #pragma unroll
            for (int nb = 0; nb < 8; nb++) {
                const float* bp = &Bs[s][(kk + t4) * BST + wc * 64 + nb * 8 + g];
                bfr[nb][0] = __float_as_uint(bp[0]);
                bfr[nb][1] = __float_as_uint(bp[4 * BST]);
            }
            #pragma unroll
            for (int c = 0; c < 2; c++)
                #pragma unroll
                for (int nb = 0; nb < 8; nb++)
                    mma8(acc[c][nb], a[c], bfr[nb]);
        }
    };

    int KT = DM / GBK;
    loadregs(0);
    storeregs(0);
    __syncthreads();
    for (int t = 0; t < KT; t++) {
        if (t + 1 < KT) loadregs((t + 1) * GBK);
        compute(t & 1);
        if (t + 1 < KT) storeregs((t + 1) & 1);
        __syncthreads();
    }

    float* Zb = Z + (size_t)b * NEXP * LEN;
    #pragma unroll
    for (int c = 0; c < 2; c++) {
        #pragma unroll
        for (int nb = 0; nb < 8; nb++) {
            int l = bl + wc * 64 + nb * 8 + 2 * t4;
            #pragma unroll
            for (int h = 0; h < 2; h++) {
                int n = bm + wr * 32 + c * 16 + g + h * 8;
                if (n < NEXP) {
                    float2 o;
                    o.x = acc[c][nb][h * 2 + 0] * ZSCALE;
                    o.y = acc[c][nb][h * 2 + 1] * ZSCALE;
                    *reinterpret_cast<float2*>(Zb + (size_t)n * LEN + l) = o;
                }
            }
        }
    }
}

// ------------------------- fused sums: fw row sums + bw column partials (no in-loop syncs) ----
// grid (BSZ, NSPLIT), 256 threads. Warp w owns rows n0+w, n0+w+8, ...
__global__ void __launch_bounds__(256) sums_fused(
    const float* __restrict__ Z, const int* __restrict__ mask,
    float* __restrict__ invA, float* __restrict__ invB,
    float* __restrict__ psA, float* __restrict__ psB)
{
    __shared__ float colA[8][LEN / 32][32];   // [warp][chunk][lane]
    __shared__ float colB[8][LEN / 32][32];
    int b = blockIdx.x, s = blockIdx.y;
    int warp = threadIdx.x >> 5, lane = threadIdx.x & 31;
    int n0 = s * (NEXP / NSPLIT);

    float ca[LEN / 32] = {}, cb[LEN / 32] = {};   // per-lane column partials (cols lane + 32*c)

    for (int r = warp; r < NEXP / NSPLIT; r += 8) {
        int n = n0 + r;
        const float* zr = Z + ((size_t)b * NEXP + n) * LEN;
        const int*  mr = mask + ((size_t)b * NEXP + n) * LEN;
        float sa = 0.f, sb = 0.f;
        #pragma unroll
        for (int c = 0; c < LEN / 32; c++) {
            float z = zr[c * 32 + lane];
            int m = mr[c * 32 + lane];
            float fa = m ? fmaxf(z, 0.f) : 0.f;
            float fb = m ? fmaxf(-z, 0.f) : 0.f;
            sa += fa; sb += fb;
            ca[c] += fa; cb[c] += fb;
        }
        #pragma unroll
        for (int o = 16; o; o >>= 1) {
            sa += __shfl_down_sync(0xffffffffu, sa, o);
            sb += __shfl_down_sync(0xffffffffu, sb, o);
        }
        if (!lane) {
            invA[b * NEXP + n] = 1.f / (sa + 1e-9f);
            invB[b * NEXP + n] = 1.f / (sb + 1e-9f);
        }
    }
    #pragma unroll
    for (int c = 0; c < LEN / 32; c++) {
        colA[warp][c][lane] = ca[c];
        colB[warp][c][lane] = cb[c];
    }
    __syncthreads();
    // 256 threads: thread t reduces column l = t over 8 warps
    int l = threadIdx.x;
    int cc = l >> 5, ll = l & 31;
    float sa = 0.f, sb = 0.f;
    #pragma unroll
    for (int w = 0; w < 8; w++) {
        sa += colA[w][cc][ll];
        sb += colB[w][cc][ll];
    }
    psA[((size_t)b * NSPLIT + s) * LEN + l] = sa;
    psB[((size_t)b * NSPLIT + s) * LEN + l] = sb;
}

__global__ void bw_final(const float* __restrict__ psA, const float* __restrict__ psB,
                         float* __restrict__ invA, float* __restrict__ invB)
{
    int b = blockIdx.x, l = threadIdx.x;
    float sa = 0.f, sb = 0.f;
    for (int s = 0; s < NSPLIT; s++) {
        sa += psA[((size_t)b * NSPLIT + s) * LEN + l];
        sb += psB[((size_t)b * NSPLIT + s) * LEN + l];
    }
    invA[b * LEN + l] = 1.f / (sa + 1e-9f);
    invB[b * LEN + l] = 1.f / (sb + 1e-9f);
}

// ------------------------- forward class GEMM, tf32 dual, double-buffered, 1 sync/iter --------
__global__ void __launch_bounds__(256) classfw_tf32(
    const float* __restrict__ Z, const int* __restrict__ mask,
    const float* __restrict__ AE, const float* __restrict__ BE,
    const float* __restrict__ invA, const float* __restrict__ invB,
    const int* __restrict__ nidx, const float* __restrict__ btab,
    float* __restrict__ CA, float* __restrict__ CB)
{
    extern __shared__ float dyn[];
    int tid = threadIdx.x;
    int b  = blockIdx.z;
    int bm = blockIdx.y * 128;   // expert n
    int bn = blockIdx.x * 64;    // d
    int warp = tid >> 5, lane = tid & 31;
    int wr = warp >> 1, wc = warp & 1;
    int g = lane >> 2, t4 = lane & 3;

    float acca[2][4][4] = {}, accb[2][4][4] = {};

    float4 za[2]; int4 ma[2]; float4 ea, eb;
    int ar = tid >> 2, ac = (tid & 3) << 2;
    int rb = tid >> 4, cb = (tid & 15) << 2;

    auto loadregs = [&](int k0) {
        #pragma unroll
        for (int h = 0; h < 2; h++) {
            int n = bm + ar + h * 64; if (n >= NEXP) n = NEXP - 1;
            size_t zoff = ((size_t)b * NEXP + n) * LEN + k0 + ac;
            za[h] = *reinterpret_cast<const float4*>(Z + zoff);
            ma[h] = *reinterpret_cast<const int4*>(mask + zoff);
        }
        size_t eoff = ((size_t)b * LEN + k0 + rb) * DM + bn + cb;
        ea = *reinterpret_cast<const float4*>(AE + eoff);
        eb = *reinterpret_cast<const float4*>(BE + eoff);
    };
    auto storeregs = [&](int s) {
        float* Aa = dyn + s * CSTAGE;
        float* Ab = Aa + 128 * ASTC;
        float* Ba = Ab + 128 * ASTC;
        float* Bb = Ba + 16 * BSTC;
        #pragma unroll
        for (int h = 0; h < 2; h++) {
            int r = ar + h * 64;
            float* pa = &Aa[r * ASTC + ac];
            float* pb = &Ab[r * ASTC + ac];
            pa[0] = ma[h].x ? rna(fmaxf(za[h].x, 0.f)) : 0.f;
            pb[0] = ma[h].x ? rna(fmaxf(-za[h].x, 0.f)) : 0.f;
            pa[1] = ma[h].y ? rna(fmaxf(za[h].y, 0.f)) : 0.f;
            pb[1] = ma[h].y ? rna(fmaxf(-za[h].y, 0.f)) : 0.f;
            pa[2] = ma[h].z ? rna(fmaxf(za[h].z, 0.f)) : 0.f;
            pb[2] = ma[h].z ? rna(fmaxf(-za[h].z, 0.f)) : 0.f;
            pa[3] = ma[h].w ? rna(fmaxf(za[h].w, 0.f)) : 0.f;
            pb[3] = ma[h].w ? rna(fmaxf(-za[h].w, 0.f)) : 0.f;
        }
        *reinterpret_cast<float4*>(&Ba[rb * BSTC + cb]) = ea;
        *reinterpret_cast<float4*>(&Bb[rb * BSTC + cb]) = eb;
    };
    auto compute = [&](int s) {
        const float* Aa = dyn + s * CSTAGE;
        const float* Ab = Aa + 128 * ASTC;
        const float* Ba = Ab + 128 * ASTC;
        const float* Bb = Ba + 16 * BSTC;
        #pragma unroll
        for (int kk = 0; kk < 16; kk += 8) {
            uint32_t afa[2][4], afb[2][4], bfa[4][2], bfb[4][2];
            #pragma unroll
            for (int c = 0; c < 2; c++) {
                const float* ap = &Aa[(wr * 32 + c * 16 + g) * ASTC + kk + t4];
                const float* bp = &Ab[(wr * 32 + c * 16 + g) * ASTC + kk + t4];
                afa[c][0] = __float_as_uint(ap[0]);
                afa[c][1] = __float_as_uint(ap[8 * ASTC]);
                afa[c][2] = __float_as_uint(ap[4]);
                afa[c][3] = __float_as_uint(ap[8 * ASTC + 4]);
                afb[c][0] = __float_as_uint(bp[0]);
                afb[c][1] = __float_as_uint(bp[8 * ASTC]);
                afb[c][2] = __float_as_uint(bp[4]);
                afb[c][3] = __float_as_uint(bp[8 * ASTC + 4]);
            }
            #pragma unroll
            for (int nb = 0; nb < 4; nb++) {
                const float* bpa = &Ba[(kk + t4) * BSTC + wc * 32 + nb * 8 + g];
                const float* bpb = &Bb[(kk + t4) * BSTC + wc * 32 + nb * 8 + g];
                bfa[nb][0] = __float_as_uint(bpa[0]);
                bfa[nb][1] = __float_as_uint(bpa[4 * BSTC]);
                bfb[nb][0] = __float_as_uint(bpb[0]);
                bfb[nb][1] = __float_as_uint(bpb[4 * BSTC]);
            }
            #pragma unroll
            for (int c = 0; c < 2; c++)
                #pragma unroll
                for (int nb = 0; nb < 4; nb++) {
                    mma8(acca[c][nb], afa[c], bfa[nb]);
                    mma8(accb[c][nb], afb[c], bfb[nb]);
                }
        }
    };

    loadregs(0);
    storeregs(0);
    __syncthreads();
    const int KT = LEN / 16;   // 16
    for (int t = 0; t < KT; t++) {
        if (t + 1 < KT) loadregs((t + 1) * 16);
        compute(t & 1);
        if (t + 1 < KT) storeregs((t + 1) & 1);
        __syncthreads();
    }

    #pragma unroll
    for (int c = 0; c < 2; c++) {
        #pragma unroll
        for (int h = 0; h < 2; h++) {
            int n = bm + wr * 32 + c * 16 + g + h * 8;
            if (n >= NEXP) continue;
            float ia = invA[b * NEXP + n];
            float ib = invB[b * NEXP + n];
            int qi = nidx[b * NEXP + n];
            #pragma unroll
            for (int nb = 0; nb < 4; nb++) {
                int d0 = bn + wc * 32 + nb * 8 + 2 * t4;
                float2 bi = *reinterpret_cast<const float2*>(btab + (size_t)qi * DM + d0);
                size_t off = ((size_t)b * NEXP + n) * DM + d0;
                float2 oa, ob;
                oa.x = rna(acca[c][nb][h * 2 + 0] * ia + bi.x);
                oa.y = rna(acca[c][nb][h * 2 + 1] * ia + bi.y);
                ob.x = rna(accb[c][nb][h * 2 + 0] * ib + bi.x);
                ob.y = rna(accb[c][nb][h * 2 + 1] * ib + bi.y);
                *reinterpret_cast<float2*>(CA + off) = oa;
                *reinterpret_cast<float2*>(CB + off) = ob;
            }
        }
    }
}

// ------------------------- backward class GEMM, tf32 dual, double-buffered, 1 sync/iter -------
__global__ void __launch_bounds__(256) classbw_tf32(
    const float* __restrict__ Z, const int* __restrict__ mask,
    const float* __restrict__ CA, const float* __restrict__ CB,
    const float* __restrict__ invA, const float* __restrict__ invB,
    const float* __restrict__ SELp, const float* __restrict__ X,
    float* __restrict__ X1)
{
    extern __shared__ float dyn[];
    int tid = threadIdx.x;
    int b  = blockIdx.z;
    int bl = blockIdx.y * 128;   // l
    int bn = blockIdx.x * 64;    // d
    int warp = tid >> 5, lane = tid & 31;
    int wr = warp >> 1, wc = warp & 1;
    int g = lane >> 2, t4 = lane & 3;

    float acca[2][4][4] = {}, accb[2][4][4] = {};

    float4 za[2]; int4 ma[2]; float4 ca, cbv;
    int rn0 = tid >> 5, cl0 = (tid & 31) << 2;     // A loads: 8 n-rows/half, 128 l-cols
    int rb = tid >> 4, cb = (tid & 15) << 2;

    auto loadregs = [&](int k0) {
        #pragma unroll
        for (int h = 0; h < 2; h++) {
            size_t zoff = ((size_t)b * NEXP + k0 + rn0 + h * 8) * LEN + bl + cl0;
            za[h] = *reinterpret_cast<const float4*>(Z + zoff);
            ma[h] = *reinterpret_cast<const int4*>(mask + zoff);
        }
        size_t coff = ((size_t)b * NEXP + k0 + rb) * DM + bn + cb;
        ca  = *reinterpret_cast<const float4*>(CA + coff);
        cbv = *reinterpret_cast<const float4*>(CB + coff);
    };
    auto storeregs = [&](int s) {
        float* Aa = dyn + s * CSTAGE;
        float* Ab = Aa + 128 * ASTC;
        float* Ba = Ab + 128 * ASTC;
        float* Bb = Ba + 16 * BSTC;
        #pragma unroll
        for (int h = 0; h < 2; h++) {
            int rn = rn0 + h * 8;
            // transposed store: A[m=l][k=n]
            Aa[(cl0 + 0) * ASTC + rn] = ma[h].x ? rna(fmaxf(za[h].x, 0.f)) : 0.f;
            Ab[(cl0 + 0) * ASTC + rn] = ma[h].x ? rna(fmaxf(-za[h].x, 0.f)) : 0.f;
            Aa[(cl0 + 1) * ASTC + rn] = ma[h].y ? rna(fmaxf(za[h].y, 0.f)) : 0.f;
            Ab[(cl0 + 1) * ASTC + rn] = ma[h].y ? rna(fmaxf(-za[h].y, 0.f)) : 0.f;
            Aa[(cl0 + 2) * ASTC + rn] = ma[h].z ? rna(fmaxf(za[h].z, 0.f)) : 0.f;
            Ab[(cl0 + 2) * ASTC + rn] = ma[h].z ? rna(fmaxf(-za[h].z, 0.f)) : 0.f;
            Aa[(cl0 + 3) * ASTC + rn] = ma[h].w ? rna(fmaxf(za[h].w, 0.f)) : 0.f;
            Ab[(cl0 + 3) * ASTC + rn] = ma[h].w ? rna(fmaxf(-za[h].w, 0.f)) : 0.f;
        }
        *reinterpret_cast<float4*>(&Ba[rb * BSTC + cb]) = ca;
        *reinterpret_cast<float4*>(&Bb[rb * BSTC + cb]) = cbv;
    };
    auto compute = [&](int s) {
        const float* Aa = dyn + s * CSTAGE;
        const float* Ab = Aa + 128 * ASTC;
        const float* Ba = Ab + 128 * ASTC;
        const float* Bb = Ba + 16 * BSTC;
        #pragma unroll
        for (int kk = 0; kk < 16; kk += 8) {
            uint32_t afa[2][4], afb[2][4], bfa[4][2], bfb[4][2];
            #pragma unroll
            for (int c = 0; c < 2; c++) {
                const float* ap = &Aa[(wr * 32 + c * 16 + g) * ASTC + kk + t4];
                const float* bp = &Ab[(wr * 32 + c * 16 + g) * ASTC + kk + t4];
                afa[c][0] = __float_as_uint(ap[0]);
                afa[c][1] = __float_as_uint(ap[8 * ASTC]);
                afa[c][2] = __float_as_uint(ap[4]);
                afa[c][3] = __float_as_uint(ap[8 * ASTC + 4]);
                afb[c][0] = __float_as_uint(bp[0]);
                afb[c][1] = __float_as_uint(bp[8 * ASTC]);
                afb[c][2] = __float_as_uint(bp[4]);
                afb[c][3] = __float_as_uint(bp[8 * ASTC + 4]);
            }
            #pragma unroll
            for (int nb = 0; nb < 4; nb++) {
                const float* bpa = &Ba[(kk + t4) * BSTC + wc * 32 + nb * 8 + g];
                const float* bpb = &Bb[(kk + t4) * BSTC + wc * 32 + nb * 8 + g];
                bfa[nb][0] = __float_as_uint(bpa[0]);
                bfa[nb][1] = __float_as_uint(bpa[4 * BSTC]);
                bfb[nb][0] = __float_as_uint(bpb[0]);
                bfb[nb][1] = __float_as_uint(bpb[4 * BSTC]);
            }
            #pragma unroll
            for (int c = 0; c < 2; c++)
                #pragma unroll
                for (int nb = 0; nb < 4; nb++) {
                    mma8(acca[c][nb], afa[c], bfa[nb]);
                    mma8(accb[c][nb], afb[c], bfb[nb]);
                }
        }
    };

    loadregs(0);
    storeregs(0);
    __syncthreads();
    const int KT = NEXP / 16;    // 62
    for (int t = 0; t < KT; t++) {
        if (t + 1 < KT) loadregs((t + 1) * 16);
        compute(t & 1);
        if (t + 1 < KT) storeregs((t + 1) & 1);
        __syncthreads();
    }

    #pragma unroll
    for (int c = 0; c < 2; c++) {
        #pragma unroll
        for (int h = 0; h < 2; h++) {
            int l = bl + wr * 32 + c * 16 + g + h * 8;
            float ia = invA[b * LEN + l];
            float ib = invB[b * LEN + l];
            #pragma unroll
            for (int nb = 0; nb < 4; nb++) {
                int d0 = bn + wc * 32 + nb * 8 + 2 * t4;
                size_t off = ((size_t)b * LEN + l) * DM + d0;
                float2 s2 = *reinterpret_cast<const float2*>(SELp + off);
                float2 x2 = *reinterpret_cast<const float2*>(X + off);
                float2 o;
                o.x = x2.x + s2.x * (acca[c][nb][h * 2 + 0] * ia)
                           + (1.f - s2.x) * (accb[c][nb][h * 2 + 0] * ib);
                o.y = x2.y + s2.y * (acca[c][nb][h * 2 + 1] * ia)
                           + (1.f - s2.y) * (accb[c][nb][h * 2 + 1] * ib);
                *reinterpret_cast<float2*>(X1 + off) = o;
            }
        }
    }
}

// ------------------------- launch -------------------------
extern "C" void kernel_launch(void* const* d_in, const int* in_sizes, int n_in,
                              void* d_out, int out_size)
{
    const float* x     = (const float*)d_in[0];
    const int*   nidx  = (const int*)d_in[1];
    const int*   mask  = (const int*)d_in[2];
    const float* ln1_g = (const float*)d_in[3];
    const float* ln1_b = (const float*)d_in[4];
    const float* ln2_g = (const float*)d_in[5];
    const float* ln2_b = (const float*)d_in[6];
    const float* q_tab = (const float*)d_in[7];
    const float* b_tab = (const float*)d_in[8];
    const float* Wk  = (const float*)d_in[9];  const float* bk   = (const float*)d_in[10];
    const float* Wa  = (const float*)d_in[11]; const float* ba   = (const float*)d_in[12];
    const float* Wa1 = (const float*)d_in[13]; const float* ba1  = (const float*)d_in[14];
    const float* Wb  = (const float*)d_in[15]; const float* bb   = (const float*)d_in[16];
    const float* Wb1 = (const float*)d_in[17]; const float* bb1  = (const float*)d_in[18];
    const float* Ws  = (const float*)d_in[19]; const float* bsel = (const float*)d_in[20];
    const float* Wf1 = (const float*)d_in[21]; const float* bf1  = (const float*)d_in[22];
    const float* Wf2 = (const float*)d_in[23]; const float* bf2  = (const float*)d_in[24];
    float* out = (float*)d_out;

    float *pX2, *pXK, *pEA0, *pEB0, *pAE, *pBE, *pSEL, *pX1, *pZ, *pCA, *pCB, *pH;
    float *pIAf, *pIBf, *pPA, *pPB, *pIAb, *pIBb, *pWR, *pQR;
    cudaGetSymbolAddress((void**)&pX2, g_X2);
    cudaGetSymbolAddress((void**)&pXK, g_XK);
    cudaGetSymbolAddress((void**)&pEA0, g_EA0);
    cudaGetSymbolAddress((void**)&pEB0, g_EB0);
    cudaGetSymbolAddress((void**)&pAE, g_AE);
    cudaGetSymbolAddress((void**)&pBE, g_BE);
    cudaGetSymbolAddress((void**)&pSEL, g_SEL);
    cudaGetSymbolAddress((void**)&pX1, g_X1);
    cudaGetSymbolAddress((void**)&pZ, g_Z);
    cudaGetSymbolAddress((void**)&pCA, g_CA);
    cudaGetSymbolAddress((void**)&pCB, g_CB);
    cudaGetSymbolAddress((void**)&pH, g_H);
    cudaGetSymbolAddress((void**)&pIAf, g_IAf);
    cudaGetSymbolAddress((void**)&pIBf, g_IBf);
    cudaGetSymbolAddress((void**)&pPA, g_PA);
    cudaGetSymbolAddress((void**)&pPB, g_PB);
    cudaGetSymbolAddress((void**)&pIAb, g_IAb);
    cudaGetSymbolAddress((void**)&pIBb, g_IBb);
    cudaGetSymbolAddress((void**)&pWR, g_WR);
    cudaGetSymbolAddress((void**)&pQR, g_QR);

    float* WkR  = pWR;
    float* WaR  = pWR + 262144;
    float* WbR  = pWR + 524288;
    float* WsR  = pWR + 786432;
    float* Wa1R = pWR + 1048576;
    float* Wb1R = pWR + 1310720;
    float* Wf1R = pWR + 1572864;
    float* Wf2R = pWR + 2621440;

    static int smem_set = 0;
    if (!smem_set) {
        cudaFuncSetAttribute(classfw_tf32, cudaFuncAttributeMaxDynamicSharedMemorySize, CSMEM);
        cudaFuncSetAttribute(classbw_tf32, cudaFuncAttributeMaxDynamicSharedMemorySize, CSMEM);
        smem_set = 1;
    }

    // 0. round weights + q_tab to tf32 (RNA)
    rnd_kernel<<<256, 256>>>(Wk,  WkR,  65536);
    rnd_kernel<<<256, 256>>>(Wa,  WaR,  65536);
    rnd_kernel<<<256, 256>>>(Wb,  WbR,  65536);
    rnd_kernel<<<256, 256>>>(Ws,  WsR,  65536);
    rnd_kernel<<<256, 256>>>(Wa1, Wa1R, 65536);
    rnd_kernel<<<256, 256>>>(Wb1, Wb1R, 65536);
    rnd_kernel<<<1024, 256>>>(Wf1, Wf1R, 262144);
    rnd_kernel<<<1024, 256>>>(Wf2, Wf2R, 262144);
    rnd_kernel<<<496, 256>>>(q_tab, pQR, 126976);

    // 1. LN1 (rounded output -> feeds tensor GEMMs)
    ln_kernel<true><<<M1, 128>>>(x, ln1_g, ln1_b, pX2);

    // 2. dense projections (tf32 tensor cores); AE/BE rounded for classfw
    dim3 gA(DM / GBN, M1 / GBM);
    gemm_tf32<0, true ><<<gA, 256>>>(pX2, WkR, bk, nullptr, pXK, M1, DM, DM);
    gemm_tf32<0, true ><<<gA, 256>>>(pX2, WaR, ba, nullptr, pEA0, M1, DM, DM);
    gemm_tf32<0, true ><<<gA, 256>>>(pX2, WbR, bb, nullptr, pEB0, M1, DM, DM);
    gemm_tf32<1, false><<<gA, 256>>>(pX2, WsR, bsel, nullptr, pSEL, M1, DM, DM);
    gemm_tf32<3, true ><<<gA, 256>>>(pEA0, Wa1R, ba1, pEA0, pAE, M1, DM, DM);
    gemm_tf32<3, true ><<<gA, 256>>>(pEB0, Wb1R, bb1, pEB0, pBE, M1, DM, DM);

    // 3. z = Q_exp @ XK^T / sqrt(d)   (tf32 tensor cores)
    zgemm_tf32<<<dim3(LEN / GBN, (NEXP + GBM - 1) / GBM, BSZ), 256>>>(nidx, pQR, pXK, pZ);

    // 4. normalization sums (fused fw + bw partials)
    sums_fused<<<dim3(BSZ, NSPLIT), 256>>>(pZ, mask, pIAf, pIBf, pPA, pPB);
    bw_final<<<BSZ, LEN>>>(pPA, pPB, pIAb, pIBb);

    // 5. forward classes (tf32 dual), 6. backward classes + blend + residual (tf32 dual)
    classfw_tf32<<<dim3(DM / 64, (NEXP + 127) / 128, BSZ), 256, CSMEM>>>(
        pZ, mask, pAE, pBE, pIAf, pIBf, nidx, b_tab, pCA, pCB);
    classbw_tf32<<<dim3(DM / 64, LEN / 128, BSZ), 256, CSMEM>>>(
        pZ, mask, pCA, pCB, pIAb, pIBb, pSEL, x, pX1);

    // 7. LN2 + FFN (tf32 tensor cores; residual fused into final store)
    ln_kernel<true><<<M1, 128>>>(pX1, ln2_g, ln2_b, pX2);
    gemm_tf32<2, true ><<<dim3(DFF / GBN, M1 / GBM), 256>>>(pX2, Wf1R, bf1, nullptr, pH, M1, DFF, DM);
    gemm_tf32<4, false><<<dim3(DM / GBN, M1 / GBM), 256>>>(pH, Wf2R, bf2, pX1, out, M1, DM, DFF);
}

// round 5
// speedup vs baseline: 1.1049x; 1.1049x over previous
#include <cuda_runtime.h>
#include <math.h>
#include <stdint.h>

#define BSZ  64
#define LEN  256
#define DM   512
#define DFF  2048
#define NEXP 992
#define M1   (BSZ * LEN)            // 16384
#define NSPLIT 8
#define ZSCALE 0.044194173824159216f   // 1/sqrt(512)

// dense GEMM tiling
#define GBM 128
#define GBN 128
#define GBK 16
#define AST 20    // As row stride (floats): 16 + 4 pad
#define BST 132   // Bs row stride (floats): 128 + 4 pad

// class GEMM tiling (128x64 tile, dual accumulators)
#define ASTC 17   // 16 + 1 pad
#define BSTC 68   // 64 + 4 pad
#define CSTAGE (128 * ASTC * 2 + 16 * BSTC * 2)   // floats per stage = 6528
#define CSMEM  (CSTAGE * 2 * 4)                   // bytes = 52224

// ------------------------- scratch (static device globals) -------------------------
static __device__ float g_X2  [(size_t)M1 * DM];
static __device__ float g_XK  [(size_t)M1 * DM];
static __device__ float g_EA0 [(size_t)M1 * DM];
static __device__ float g_EB0 [(size_t)M1 * DM];
static __device__ float g_AE  [(size_t)M1 * DM];
static __device__ float g_BE  [(size_t)M1 * DM];
static __device__ float g_SEL [(size_t)M1 * DM];
static __device__ float g_X1  [(size_t)M1 * DM];
static __device__ float g_ZM  [(size_t)BSZ * NEXP * LEN];   // masked, tf32-rounded z
static __device__ float g_CA  [(size_t)BSZ * NEXP * DM];
static __device__ float g_CB  [(size_t)BSZ * NEXP * DM];
static __device__ float g_H   [(size_t)M1 * DFF];
static __device__ float g_IAf [BSZ * NEXP];
static __device__ float g_IBf [BSZ * NEXP];
static __device__ float g_PA  [BSZ * NSPLIT * LEN];
static __device__ float g_PB  [BSZ * NSPLIT * LEN];
static __device__ float g_IAb [BSZ * LEN];
static __device__ float g_IBb [BSZ * LEN];
static __device__ float g_WR  [3670016];           // rounded weights
static __device__ float g_QR  [(size_t)NEXP * DM]; // rounded q_tab

// ------------------------- helpers -------------------------
__device__ __forceinline__ float rna(float x) {
    uint32_t u;
    asm("cvt.rna.tf32.f32 %0, %1;" : "=r"(u) : "f"(x));
    return __uint_as_float(u);
}

__device__ __forceinline__ void cpa16(uint32_t dst, const void* src) {
    asm volatile("cp.async.cg.shared.global [%0], [%1], 16;" :: "r"(dst), "l"(src));
}

__device__ __forceinline__ void mma8(float* d, const uint32_t* a, const uint32_t* b) {
    asm volatile(
        "mma.sync.aligned.m16n8k8.row.col.f32.tf32.tf32.f32 "
        "{%0,%1,%2,%3}, {%4,%5,%6,%7}, {%8,%9}, {%0,%1,%2,%3};"
        : "+f"(d[0]), "+f"(d[1]), "+f"(d[2]), "+f"(d[3])
        : "r"(a[0]), "r"(a[1]), "r"(a[2]), "r"(a[3]), "r"(b[0]), "r"(b[1]));
}

// round-to-tf32 elementwise pass (float4 granularity)
__global__ void rnd_kernel(const float* __restrict__ s, float* __restrict__ d, int n4)
{
    int i = blockIdx.x * blockDim.x + threadIdx.x;
    if (i < n4) {
        float4 v = reinterpret_cast<const float4*>(s)[i];
        v.x = rna(v.x); v.y = rna(v.y); v.z = rna(v.z); v.w = rna(v.w);
        reinterpret_cast<float4*>(d)[i] = v;
    }
}

// ------------------------- LayerNorm (optionally tf32-rounded output) -------------------------
template <bool RND>
__global__ void ln_kernel(const float* __restrict__ X, const float* __restrict__ G,
                          const float* __restrict__ B, float* __restrict__ O)
{
    __shared__ float sred[4];
    int row = blockIdx.x;
    int t = threadIdx.x;                       // 128 threads, 4 floats each
    const float4 v = reinterpret_cast<const float4*>(X + (size_t)row * DM)[t];
    float s = v.x + v.y + v.z + v.w;
    #pragma unroll
    for (int o = 16; o; o >>= 1) s += __shfl_down_sync(0xffffffffu, s, o);
    if ((t & 31) == 0) sred[t >> 5] = s;
    __syncthreads();
    float mu = (sred[0] + sred[1] + sred[2] + sred[3]) * (1.0f / DM);
    __syncthreads();
    float4 d;
    d.x = v.x - mu; d.y = v.y - mu; d.z = v.z - mu; d.w = v.w - mu;
    float ss = d.x * d.x + d.y * d.y + d.z * d.z + d.w * d.w;
    #pragma unroll
    for (int o = 16; o; o >>= 1) ss += __shfl_down_sync(0xffffffffu, ss, o);
    if ((t & 31) == 0) sred[t >> 5] = ss;
    __syncthreads();
    float var = (sred[0] + sred[1] + sred[2] + sred[3]) * (1.0f / DM);
    float rstd = rsqrtf(var + 1e-5f);
    const float4 g4 = reinterpret_cast<const float4*>(G)[t];
    const float4 b4 = reinterpret_cast<const float4*>(B)[t];
    float4 o4;
    o4.x = d.x * rstd * g4.x + b4.x;
    o4.y = d.y * rstd * g4.y + b4.y;
    o4.z = d.z * rstd * g4.z + b4.z;
    o4.w = d.w * rstd * g4.w + b4.w;
    if (RND) { o4.x = rna(o4.x); o4.y = rna(o4.y); o4.z = rna(o4.z); o4.w = rna(o4.w); }
    reinterpret_cast<float4*>(O + (size_t)row * DM)[t] = o4;
}

// ------------------------- tf32 tensor-core NN GEMM (128x128x16, cp.async double-buffer) ------
template <int MODE, bool RND>
__global__ void __launch_bounds__(256) gemm_tf32(
    const float* __restrict__ A, const float* __restrict__ B,
    const float* __restrict__ bias, const float* __restrict__ Dm,
    float* __restrict__ C, int M, int N, int K)
{
    __shared__ float As[2][GBM * AST];
    __shared__ float Bs[2][GBK * BST];
    int tid = threadIdx.x;
    int bm = blockIdx.y * GBM, bn = blockIdx.x * GBN;
    int warp = tid >> 5, lane = tid & 31;
    int wr = warp >> 1, wc = warp & 1;
    int g = lane >> 2, t4 = lane & 3;

    float acc[2][8][4];
    #pragma unroll
    for (int c = 0; c < 2; c++)
        #pragma unroll
        for (int nb = 0; nb < 8; nb++)
            #pragma unroll
            for (int i = 0; i < 4; i++) acc[c][nb][i] = 0.f;

    int KT = K / GBK;

    auto loadtile = [&](int s, int k0) {
        #pragma unroll
        for (int h = 0; h < 2; h++) {
            int q = tid + h * 256;
            int r = q >> 2, c = (q & 3) << 2;
            uint32_t da = (uint32_t)__cvta_generic_to_shared(&As[s][r * AST + c]);
            cpa16(da, A + (size_t)(bm + r) * K + k0 + c);
            int rb = q >> 5, cb = (q & 31) << 2;
            uint32_t db = (uint32_t)__cvta_generic_to_shared(&Bs[s][rb * BST + cb]);
            cpa16(db, B + (size_t)(k0 + rb) * N + bn + cb);
        }
        asm volatile("cp.async.commit_group;");
    };

    auto compute = [&](int s) {
        #pragma unroll
        for (int kk = 0; kk < GBK; kk += 8) {
            uint32_t a[2][4], b[8][2];
            #pragma unroll
            for (int c = 0; c < 2; c++) {
                const float* ap = &As[s][(wr * 32 + c * 16 + g) * AST + kk + t4];
                a[c][0] = __float_as_uint(ap[0]);
                a[c][1] = __float_as_uint(ap[8 * AST]);
                a[c][2] = __float_as_uint(ap[4]);
                a[c][3] = __float_as_uint(ap[8 * AST + 4]);
            }
            #pragma unroll
            for (int nb = 0; nb < 8; nb++) {
                const float* bp = &Bs[s][(kk + t4) * BST + wc * 64 + nb * 8 + g];
                b[nb][0] = __float_as_uint(bp[0]);
                b[nb][1] = __float_as_uint(bp[4 * BST]);
            }
            #pragma unroll
            for (int c = 0; c < 2; c++)
                #pragma unroll
                for (int nb = 0; nb < 8; nb++)
                    mma8(acc[c][nb], a[c], b[nb]);
        }
    };

    loadtile(0, 0);
    for (int t = 0; t < KT; t++) {
        if (t + 1 < KT) {
            loadtile((t + 1) & 1, (t + 1) * GBK);
            asm volatile("cp.async.wait_group 1;");
        } else {
            asm volatile("cp.async.wait_group 0;");
        }
        __syncthreads();
        compute(t & 1);
        __syncthreads();
    }

    #pragma unroll
    for (int c = 0; c < 2; c++) {
        #pragma unroll
        for (int nb = 0; nb < 8; nb++) {
            int n = bn + wc * 64 + nb * 8 + 2 * t4;
            float2 bi = *reinterpret_cast<const float2*>(bias + n);
            #pragma unroll
            for (int h = 0; h < 2; h++) {
                int m = bm + wr * 32 + c * 16 + g + h * 8;
                size_t off = (size_t)m * N + n;
                float v0 = acc[c][nb][h * 2 + 0] + bi.x;
                float v1 = acc[c][nb][h * 2 + 1] + bi.y;
                float2 o;
                if (MODE == 0) {
                    o.x = v0; o.y = v1;
                } else if (MODE == 1) {
                    o.x = 1.f / (1.f + expf(-v0)); o.y = 1.f / (1.f + expf(-v1));
                } else if (MODE == 2) {
                    o.x = fmaxf(v0, 0.f); o.y = fmaxf(v1, 0.f);
                } else if (MODE == 3) {
                    float2 d2 = *reinterpret_cast<const float2*>(Dm + off);
                    o.x = d2.x / (1.f + expf(-v0)); o.y = d2.y / (1.f + expf(-v1));
                } else { // MODE 4
                    float2 d2 = *reinterpret_cast<const float2*>(Dm + off);
                    o.x = d2.x + v0; o.y = d2.y + v1;
                }
                if (RND) { o.x = rna(o.x); o.y = rna(o.y); }
                *reinterpret_cast<float2*>(C + off) = o;
            }
        }
    }
}

// ------- z = gather(q_tab) @ XK^T * scale, masked + rounded epilogue -> ZM ---------
__global__ void __launch_bounds__(256) zgemm_tf32(
    const int* __restrict__ nidx, const float* __restrict__ qr,
    const float* __restrict__ XK, const int* __restrict__ mask,
    float* __restrict__ ZM)
{
    __shared__ float As[2][GBM * AST];
    __shared__ float Bs[2][GBK * BST];
    __shared__ int sidx[GBM];
    int tid = threadIdx.x;
    int b  = blockIdx.z;
    int bm = blockIdx.y * GBM;   // n (expert)
    int bl = blockIdx.x * GBN;   // l
    int warp = tid >> 5, lane = tid & 31;
    int wr = warp >> 1, wc = warp & 1;
    int g = lane >> 2, t4 = lane & 3;

    if (tid < GBM) {
        int n = bm + tid;
        sidx[tid] = nidx[b * NEXP + (n < NEXP ? n : NEXP - 1)];
    }
    __syncthreads();

    float acc[2][8][4];
    #pragma unroll
    for (int c = 0; c < 2; c++)
        #pragma unroll
        for (int nb = 0; nb < 8; nb++)
            #pragma unroll
            for (int i = 0; i < 4; i++) acc[c][nb][i] = 0.f;

    int ar = tid >> 2, ac = (tid & 3) << 2;
    float4 ra[2], rb[2];
    auto loadregs = [&](int k0) {
        #pragma unroll
        for (int h = 0; h < 2; h++) {
            int r = ar + h * 64;
            ra[h] = *reinterpret_cast<const float4*>(qr + (size_t)sidx[r] * DM + k0 + ac);
            rb[h] = *reinterpret_cast<const float4*>(XK + (size_t)(b * LEN + bl + r) * DM + k0 + ac);
        }
    };
    auto storeregs = [&](int s) {
        #pragma unroll
        for (int h = 0; h < 2; h++) {
            int r = ar + h * 64;
            *reinterpret_cast<float4*>(&As[s][r * AST + ac]) = ra[h];
            Bs[s][(ac + 0) * BST + r] = rb[h].x;
            Bs[s][(ac + 1) * BST + r] = rb[h].y;
            Bs[s][(ac + 2) * BST + r] = rb[h].z;
            Bs[s][(ac + 3) * BST + r] = rb[h].w;
        }
    };
    auto compute = [&](int s) {
        #pragma unroll
        for (int kk = 0; kk < GBK; kk += 8) {
            uint32_t a[2][4], bfr[8][2];
            #pragma unroll
            for (int c = 0; c < 2; c++) {
                const float* ap = &As[s][(wr * 32 + c * 16 + g) * AST + kk + t4];
                a[c][0] = __float_as_uint(ap[0]);
                a[c][1] = __float_as_uint(ap[8 * AST]);
                a[c][2] = __float_as_uint(ap[4]);
                a[c][3] = __float_as_uint(ap[8 * AST + 4]);
            }
            #pragma unroll
            for (int nb = 0; nb < 8; nb++) {
                const float* bp = &Bs[s][(kk + t4) * BST + wc * 64 + nb * 8 + g];
                bfr[nb][0] = __float_as_uint(bp[0]);
                bfr[nb][1] = __float_as_uint(bp[4 * BST]);
            }
            #pragma unroll
            for (int c = 0; c < 2; c++)
                #pragma unroll
                for (int nb = 0; nb < 8; nb++)
                    mma8(acc[c][nb], a[c], bfr[nb]);
        }
    };

    int KT = DM / GBK;
    loadregs(0);
    storeregs(0);
    __syncthreads();
    for (int t = 0; t < KT; t++) {
        if (t + 1 < KT) loadregs((t + 1) * GBK);
        compute(t & 1);
        if (t + 1 < KT) storeregs((t + 1) & 1);
        __syncthreads();
    }

    float* Zb = ZM + (size_t)b * NEXP * LEN;
    const int* Mb = mask + (size_t)b * NEXP * LEN;
    #pragma unroll
    for (int c = 0; c < 2; c++) {
        #pragma unroll
        for (int nb = 0; nb < 8; nb++) {
            int l = bl + wc * 64 + nb * 8 + 2 * t4;
            #pragma unroll
            for (int h = 0; h < 2; h++) {
                int n = bm + wr * 32 + c * 16 + g + h * 8;
                if (n < NEXP) {
                    size_t off = (size_t)n * LEN + l;
                    int2 m2 = *reinterpret_cast<const int2*>(Mb + off);
                    float2 o;
                    o.x = m2.x ? rna(acc[c][nb][h * 2 + 0] * ZSCALE) : 0.f;
                    o.y = m2.y ? rna(acc[c][nb][h * 2 + 1] * ZSCALE) : 0.f;
                    *reinterpret_cast<float2*>(Zb + off) = o;
                }
            }
        }
    }
}

// ------------------------- fused sums on ZM (fw row sums + bw column partials) ----------------
__global__ void __launch_bounds__(256) sums_fused(
    const float* __restrict__ ZM,
    float* __restrict__ invA, float* __restrict__ invB,
    float* __restrict__ psA, float* __restrict__ psB)
{
    __shared__ float colA[8][LEN / 32][32];
    __shared__ float colB[8][LEN / 32][32];
    int b = blockIdx.x, s = blockIdx.y;
    int warp = threadIdx.x >> 5, lane = threadIdx.x & 31;
    int n0 = s * (NEXP / NSPLIT);

    float ca[LEN / 32] = {}, cb[LEN / 32] = {};

    for (int r = warp; r < NEXP / NSPLIT; r += 8) {
        int n = n0 + r;
        const float* zr = ZM + ((size_t)b * NEXP + n) * LEN;
        float sa = 0.f, sb = 0.f;
        #pragma unroll
        for (int c = 0; c < LEN / 32; c++) {
            float z = zr[c * 32 + lane];
            float fa = fmaxf(z, 0.f);
            float fb = fmaxf(-z, 0.f);
            sa += fa; sb += fb;
            ca[c] += fa; cb[c] += fb;
        }
        #pragma unroll
        for (int o = 16; o; o >>= 1) {
            sa += __shfl_down_sync(0xffffffffu, sa, o);
            sb += __shfl_down_sync(0xffffffffu, sb, o);
        }
        if (!lane) {
            invA[b * NEXP + n] = 1.f / (sa + 1e-9f);
            invB[b * NEXP + n] = 1.f / (sb + 1e-9f);
        }
    }
    #pragma unroll
    for (int c = 0; c < LEN / 32; c++) {
        colA[warp][c][lane] = ca[c];
        colB[warp][c][lane] = cb[c];
    }
    __syncthreads();
    int l = threadIdx.x;
    int cc = l >> 5, ll = l & 31;
    float sa = 0.f, sb = 0.f;
    #pragma unroll
    for (int w = 0; w < 8; w++) {
        sa += colA[w][cc][ll];
        sb += colB[w][cc][ll];
    }
    psA[((size_t)b * NSPLIT + s) * LEN + l] = sa;
    psB[((size_t)b * NSPLIT + s) * LEN + l] = sb;
}

__global__ void bw_final(const float* __restrict__ psA, const float* __restrict__ psB,
                         float* __restrict__ invA, float* __restrict__ invB)
{
    int b = blockIdx.x, l = threadIdx.x;
    float sa = 0.f, sb = 0.f;
    for (int s = 0; s < NSPLIT; s++) {
        sa += psA[((size_t)b * NSPLIT + s) * LEN + l];
        sb += psB[((size_t)b * NSPLIT + s) * LEN + l];
    }
    invA[b * LEN + l] = 1.f / (sa + 1e-9f);
    invB[b * LEN + l] = 1.f / (sb + 1e-9f);
}

// ------------------------- forward class GEMM, tf32 dual, double-buffered, ZM input -----------
__global__ void __launch_bounds__(256) classfw_tf32(
    const float* __restrict__ ZM,
    const float* __restrict__ AE, const float* __restrict__ BE,
    const float* __restrict__ invA, const float* __restrict__ invB,
    const int* __restrict__ nidx, const float* __restrict__ btab,
    float* __restrict__ CA, float* __restrict__ CB)
{
    extern __shared__ float dyn[];
    int tid = threadIdx.x;
    int b  = blockIdx.z;
    int bm = blockIdx.y * 128;   // expert n
    int bn = blockIdx.x * 64;    // d
    int warp = tid >> 5, lane = tid & 31;
    int wr = warp >> 1, wc = warp & 1;
    int g = lane >> 2, t4 = lane & 3;

    float acca[2][4][4] = {}, accb[2][4][4] = {};

    float4 za[2]; float4 ea, eb;
    int ar = tid >> 2, ac = (tid & 3) << 2;
    int rb = tid >> 4, cb = (tid & 15) << 2;

    auto loadregs = [&](int k0) {
        #pragma unroll
        for (int h = 0; h < 2; h++) {
            int n = bm + ar + h * 64; if (n >= NEXP) n = NEXP - 1;
            za[h] = *reinterpret_cast<const float4*>(ZM + ((size_t)b * NEXP + n) * LEN + k0 + ac);
        }
        size_t eoff = ((size_t)b * LEN + k0 + rb) * DM + bn + cb;
        ea = *reinterpret_cast<const float4*>(AE + eoff);
        eb = *reinterpret_cast<const float4*>(BE + eoff);
    };
    auto storeregs = [&](int s) {
        float* Aa = dyn + s * CSTAGE;
        float* Ab = Aa + 128 * ASTC;
        float* Ba = Ab + 128 * ASTC;
        float* Bb = Ba + 16 * BSTC;
        #pragma unroll
        for (int h = 0; h < 2; h++) {
            int r = ar + h * 64;
            float* pa = &Aa[r * ASTC + ac];
            float* pb = &Ab[r * ASTC + ac];
            pa[0] = fmaxf(za[h].x, 0.f);  pb[0] = fmaxf(-za[h].x, 0.f);
            pa[1] = fmaxf(za[h].y, 0.f);  pb[1] = fmaxf(-za[h].y, 0.f);
            pa[2] = fmaxf(za[h].z, 0.f);  pb[2] = fmaxf(-za[h].z, 0.f);
            pa[3] = fmaxf(za[h].w, 0.f);  pb[3] = fmaxf(-za[h].w, 0.f);
        }
        *reinterpret_cast<float4*>(&Ba[rb * BSTC + cb]) = ea;
        *reinterpret_cast<float4*>(&Bb[rb * BSTC + cb]) = eb;
    };
    auto compute = [&](int s) {
        const float* Aa = dyn + s * CSTAGE;
        const float* Ab = Aa + 128 * ASTC;
        const float* Ba = Ab + 128 * ASTC;
        const float* Bb = Ba + 16 * BSTC;
        #pragma unroll
        for (int kk = 0; kk < 16; kk += 8) {
            uint32_t afa[2][4], afb[2][4], bfa[4][2], bfb[4][2];
            #pragma unroll
            for (int c = 0; c < 2; c++) {
                const float* ap = &Aa[(wr * 32 + c * 16 + g) * ASTC + kk + t4];
                const float* bp = &Ab[(wr * 32 + c * 16 + g) * ASTC + kk + t4];
                afa[c][0] = __float_as_uint(ap[0]);
                afa[c][1] = __float_as_uint(ap[8 * ASTC]);
                afa[c][2] = __float_as_uint(ap[4]);
                afa[c][3] = __float_as_uint(ap[8 * ASTC + 4]);
                afb[c][0] = __float_as_uint(bp[0]);
                afb[c][1] = __float_as_uint(bp[8 * ASTC]);
                afb[c][2] = __float_as_uint(bp[4]);
                afb[c][3] = __float_as_uint(bp[8 * ASTC + 4]);
            }
            #pragma unroll
            for (int nb = 0; nb < 4; nb++) {
                const float* bpa = &Ba[(kk + t4) * BSTC + wc * 32 + nb * 8 + g];
                const float* bpb = &Bb[(kk + t4) * BSTC + wc * 32 + nb * 8 + g];
                bfa[nb][0] = __float_as_uint(bpa[0]);
                bfa[nb][1] = __float_as_uint(bpa[4 * BSTC]);
                bfb[nb][0] = __float_as_uint(bpb[0]);
                bfb[nb][1] = __float_as_uint(bpb[4 * BSTC]);
            }
            #pragma unroll
            for (int c = 0; c < 2; c++)
                #pragma unroll
                for (int nb = 0; nb < 4; nb++) {
                    mma8(acca[c][nb], afa[c], bfa[nb]);
                    mma8(accb[c][nb], afb[c], bfb[nb]);
                }
        }
    };

    loadregs(0);
    storeregs(0);
    __syncthreads();
    const int KT = LEN / 16;   // 16
    for (int t = 0; t < KT; t++) {
        if (t + 1 < KT) loadregs((t + 1) * 16);
        compute(t & 1);
        if (t + 1 < KT) storeregs((t + 1) & 1);
        __syncthreads();
    }

    #pragma unroll
    for (int c = 0; c < 2; c++) {
        #pragma unroll
        for (int h = 0; h < 2; h++) {
            int n = bm + wr * 32 + c * 16 + g + h * 8;
            if (n >= NEXP) continue;
            float ia = invA[b * NEXP + n];
            float ib = invB[b * NEXP + n];
            int qi = nidx[b * NEXP + n];
            #pragma unroll
            for (int nb = 0; nb < 4; nb++) {
                int d0 = bn + wc * 32 + nb * 8 + 2 * t4;
                float2 bi = *reinterpret_cast<const float2*>(btab + (size_t)qi * DM + d0);
                size_t off = ((size_t)b * NEXP + n) * DM + d0;
                float2 oa, ob;
                oa.x = rna(acca[c][nb][h * 2 + 0] * ia + bi.x);
                oa.y = rna(acca[c][nb][h * 2 + 1] * ia + bi.y);
                ob.x = rna(accb[c][nb][h * 2 + 0] * ib + bi.x);
                ob.y = rna(accb[c][nb][h * 2 + 1] * ib + bi.y);
                *reinterpret_cast<float2*>(CA + off) = oa;
                *reinterpret_cast<float2*>(CB + off) = ob;
            }
        }
    }
}

// ------------------------- backward class GEMM, tf32 dual, double-buffered, ZM input ----------
__global__ void __launch_bounds__(256) classbw_tf32(
    const float* __restrict__ ZM,
    const float* __restrict__ CA, const float* __restrict__ CB,
    const float* __restrict__ invA, const float* __restrict__ invB,
    const float* __restrict__ SELp, const float* __restrict__ X,
    float* __restrict__ X1)
{
    extern __shared__ float dyn[];
    int tid = threadIdx.x;
    int b  = blockIdx.z;
    int bl = blockIdx.y * 128;   // l
    int bn = blockIdx.x * 64;    // d
    int warp = tid >> 5, lane = tid & 31;
    int wr = warp >> 1, wc = warp & 1;
    int g = lane >> 2, t4 = lane & 3;

    float acca[2][4][4] = {}, accb[2][4][4] = {};

    float4 za[2]; float4 ca, cbv;
    int rn0 = tid >> 5, cl0 = (tid & 31) << 2;
    int rb = tid >> 4, cb = (tid & 15) << 2;

    auto loadregs = [&](int k0) {
        #pragma unroll
        for (int h = 0; h < 2; h++) {
            size_t zoff = ((size_t)b * NEXP + k0 + rn0 + h * 8) * LEN + bl + cl0;
            za[h] = *reinterpret_cast<const float4*>(ZM + zoff);
        }
        size_t coff = ((size_t)b * NEXP + k0 + rb) * DM + bn + cb;
        ca  = *reinterpret_cast<const float4*>(CA + coff);
        cbv = *reinterpret_cast<const float4*>(CB + coff);
    };
    auto storeregs = [&](int s) {
        float* Aa = dyn + s * CSTAGE;
        float* Ab = Aa + 128 * ASTC;
        float* Ba = Ab + 128 * ASTC;
        float* Bb = Ba + 16 * BSTC;
        #pragma unroll
        for (int h = 0; h < 2; h++) {
            int rn = rn0 + h * 8;
            // transposed store: A[m=l][k=n]
            Aa[(cl0 + 0) * ASTC + rn] = fmaxf(za[h].x, 0.f);
            Ab[(cl0 + 0) * ASTC + rn] = fmaxf(-za[h].x, 0.f);
            Aa[(cl0 + 1) * ASTC + rn] = fmaxf(za[h].y, 0.f);
            Ab[(cl0 + 1) * ASTC + rn] = fmaxf(-za[h].y, 0.f);
            Aa[(cl0 + 2) * ASTC + rn] = fmaxf(za[h].z, 0.f);
            Ab[(cl0 + 2) * ASTC + rn] = fmaxf(-za[h].z, 0.f);
            Aa[(cl0 + 3) * ASTC + rn] = fmaxf(za[h].w, 0.f);
            Ab[(cl0 + 3) * ASTC + rn] = fmaxf(-za[h].w, 0.f);
        }
        *reinterpret_cast<float4*>(&Ba[rb * BSTC + cb]) = ca;
        *reinterpret_cast<float4*>(&Bb[rb * BSTC + cb]) = cbv;
    };
    auto compute = [&](int s) {
        const float* Aa = dyn + s * CSTAGE;
        const float* Ab = Aa + 128 * ASTC;
        const float* Ba = Ab + 128 * ASTC;
        const float* Bb = Ba + 16 * BSTC;
        #pragma unroll
        for (int kk = 0; kk < 16; kk += 8) {
            uint32_t afa[2][4], afb[2][4], bfa[4][2], bfb[4][2];
            #pragma unroll
            for (int c = 0; c < 2; c++) {
                const float* ap = &Aa[(wr * 32 + c * 16 + g) * ASTC + kk + t4];
                const float* bp = &Ab[(wr * 32 + c * 16 + g) * ASTC + kk + t4];
                afa[c][0] = __float_as_uint(ap[0]);
                afa[c][1] = __float_as_uint(ap[8 * ASTC]);
                afa[c][2] = __float_as_uint(ap[4]);
                afa[c][3] = __float_as_uint(ap[8 * ASTC + 4]);
                afb[c][0] = __float_as_uint(bp[0]);
                afb[c][1] = __float_as_uint(bp[8 * ASTC]);
                afb[c][2] = __float_as_uint(bp[4]);
                afb[c][3] = __float_as_uint(bp[8 * ASTC + 4]);
            }
            #pragma unroll
            for (int nb = 0; nb < 4; nb++) {
                const float* bpa = &Ba[(kk + t4) * BSTC + wc * 32 + nb * 8 + g];
                const float* bpb = &Bb[(kk + t4) * BSTC + wc * 32 + nb * 8 + g];
                bfa[nb][0] = __float_as_uint(bpa[0]);
                bfa[nb][1] = __float_as_uint(bpa[4 * BSTC]);
                bfb[nb][0] = __float_as_uint(bpb[0]);
                bfb[nb][1] = __float_as_uint(bpb[4 * BSTC]);
            }
            #pragma unroll
            for (int c = 0; c < 2; c++)
                #pragma unroll
                for (int nb = 0; nb < 4; nb++) {
                    mma8(acca[c][nb], afa[c], bfa[nb]);
                    mma8(accb[c][nb], afb[c], bfb[nb]);
                }
        }
    };

    loadregs(0);
    storeregs(0);
    __syncthreads();
    const int KT = NEXP / 16;    // 62
    for (int t = 0; t < KT; t++) {
        if (t + 1 < KT) loadregs((t + 1) * 16);
        compute(t & 1);
        if (t + 1 < KT) storeregs((t + 1) & 1);
        __syncthreads();
    }

    #pragma unroll
    for (int c = 0; c < 2; c++) {
        #pragma unroll
        for (int h = 0; h < 2; h++) {
            int l = bl + wr * 32 + c * 16 + g + h * 8;
            float ia = invA[b * LEN + l];
            float ib = invB[b * LEN + l];
            #pragma unroll
            for (int nb = 0; nb < 4; nb++) {
                int d0 = bn + wc * 32 + nb * 8 + 2 * t4;
                size_t off = ((size_t)b * LEN + l) * DM + d0;
                float2 s2 = *reinterpret_cast<const float2*>(SELp + off);
                float2 x2 = *reinterpret_cast<const float2*>(X + off);
                float2 o;
                o.x = x2.x + s2.x * (acca[c][nb][h * 2 + 0] * ia)
                           + (1.f - s2.x) * (accb[c][nb][h * 2 + 0] * ib);
                o.y = x2.y + s2.y * (acca[c][nb][h * 2 + 1] * ia)
                           + (1.f - s2.y) * (accb[c][nb][h * 2 + 1] * ib);
                *reinterpret_cast<float2*>(X1 + off) = o;
            }
        }
    }
}

// ------------------------- launch -------------------------
extern "C" void kernel_launch(void* const* d_in, const int* in_sizes, int n_in,
                              void* d_out, int out_size)
{
    const float* x     = (const float*)d_in[0];
    const int*   nidx  = (const int*)d_in[1];
    const int*   mask  = (const int*)d_in[2];
    const float* ln1_g = (const float*)d_in[3];
    const float* ln1_b = (const float*)d_in[4];
    const float* ln2_g = (const float*)d_in[5];
    const float* ln2_b = (const float*)d_in[6];
    const float* q_tab = (const float*)d_in[7];
    const float* b_tab = (const float*)d_in[8];
    const float* Wk  = (const float*)d_in[9];  const float* bk   = (const float*)d_in[10];
    const float* Wa  = (const float*)d_in[11]; const float* ba   = (const float*)d_in[12];
    const float* Wa1 = (const float*)d_in[13]; const float* ba1  = (const float*)d_in[14];
    const float* Wb  = (const float*)d_in[15]; const float* bb   = (const float*)d_in[16];
    const float* Wb1 = (const float*)d_in[17]; const float* bb1  = (const float*)d_in[18];
    const float* Ws  = (const float*)d_in[19]; const float* bsel = (const float*)d_in[20];
    const float* Wf1 = (const float*)d_in[21]; const float* bf1  = (const float*)d_in[22];
    const float* Wf2 = (const float*)d_in[23]; const float* bf2  = (const float*)d_in[24];
    float* out = (float*)d_out;

    float *pX2, *pXK, *pEA0, *pEB0, *pAE, *pBE, *pSEL, *pX1, *pZM, *pCA, *pCB, *pH;
    float *pIAf, *pIBf, *pPA, *pPB, *pIAb, *pIBb, *pWR, *pQR;
    cudaGetSymbolAddress((void**)&pX2, g_X2);
    cudaGetSymbolAddress((void**)&pXK, g_XK);
    cudaGetSymbolAddress((void**)&pEA0, g_EA0);
    cudaGetSymbolAddress((void**)&pEB0, g_EB0);
    cudaGetSymbolAddress((void**)&pAE, g_AE);
    cudaGetSymbolAddress((void**)&pBE, g_BE);
    cudaGetSymbolAddress((void**)&pSEL, g_SEL);
    cudaGetSymbolAddress((void**)&pX1, g_X1);
    cudaGetSymbolAddress((void**)&pZM, g_ZM);
    cudaGetSymbolAddress((void**)&pCA, g_CA);
    cudaGetSymbolAddress((void**)&pCB, g_CB);
    cudaGetSymbolAddress((void**)&pH, g_H);
    cudaGetSymbolAddress((void**)&pIAf, g_IAf);
    cudaGetSymbolAddress((void**)&pIBf, g_IBf);
    cudaGetSymbolAddress((void**)&pPA, g_PA);
    cudaGetSymbolAddress((void**)&pPB, g_PB);
    cudaGetSymbolAddress((void**)&pIAb, g_IAb);
    cudaGetSymbolAddress((void**)&pIBb, g_IBb);
    cudaGetSymbolAddress((void**)&pWR, g_WR);
    cudaGetSymbolAddress((void**)&pQR, g_QR);

    float* WkR  = pWR;
    float* WaR  = pWR + 262144;
    float* WbR  = pWR + 524288;
    float* WsR  = pWR + 786432;
    float* Wa1R = pWR + 1048576;
    float* Wb1R = pWR + 1310720;
    float* Wf1R = pWR + 1572864;
    float* Wf2R = pWR + 2621440;

    static int smem_set = 0;
    if (!smem_set) {
        cudaFuncSetAttribute(classfw_tf32, cudaFuncAttributeMaxDynamicSharedMemorySize, CSMEM);
        cudaFuncSetAttribute(classbw_tf32, cudaFuncAttributeMaxDynamicSharedMemorySize, CSMEM);
        smem_set = 1;
    }

    // Launch order is arranged so ncu's fixed `-s 5 -c 1` profiles zgemm_tf32 (launch index 5).
    rnd_kernel<<<256, 256>>>(Wk,  WkR,  65536);                           // 0
    ln_kernel<true><<<M1, 128>>>(x, ln1_g, ln1_b, pX2);                   // 1
    dim3 gA(DM / GBN, M1 / GBM);
    gemm_tf32<0, true ><<<gA, 256>>>(pX2, WkR, bk, nullptr, pXK, M1, DM, DM);  // 2
    rnd_kernel<<<496, 256>>>(q_tab, pQR, 126976);                         // 3
    rnd_kernel<<<256, 256>>>(Wa,  WaR,  65536);                           // 4
    zgemm_tf32<<<dim3(LEN / GBN, (NEXP + GBM - 1) / GBM, BSZ), 256>>>(    // 5 <-- profiled
        nidx, pQR, pXK, mask, pZM);

    rnd_kernel<<<256, 256>>>(Wb,  WbR,  65536);
    rnd_kernel<<<256, 256>>>(Ws,  WsR,  65536);
    rnd_kernel<<<256, 256>>>(Wa1, Wa1R, 65536);
    rnd_kernel<<<256, 256>>>(Wb1, Wb1R, 65536);
    rnd_kernel<<<1024, 256>>>(Wf1, Wf1R, 262144);
    rnd_kernel<<<1024, 256>>>(Wf2, Wf2R, 262144);

    gemm_tf32<0, true ><<<gA, 256>>>(pX2, WaR, ba, nullptr, pEA0, M1, DM, DM);
    gemm_tf32<0, true ><<<gA, 256>>>(pX2, WbR, bb, nullptr, pEB0, M1, DM, DM);
    gemm_tf32<1, false><<<gA, 256>>>(pX2, WsR, bsel, nullptr, pSEL, M1, DM, DM);
    gemm_tf32<3, true ><<<gA, 256>>>(pEA0, Wa1R, ba1, pEA0, pAE, M1, DM, DM);
    gemm_tf32<3, true ><<<gA, 256>>>(pEB0, Wb1R, bb1, pEB0, pBE, M1, DM, DM);

    sums_fused<<<dim3(BSZ, NSPLIT), 256>>>(pZM, pIAf, pIBf, pPA, pPB);
    bw_final<<<BSZ, LEN>>>(pPA, pPB, pIAb, pIBb);

    classfw_tf32<<<dim3(DM / 64, (NEXP + 127) / 128, BSZ), 256, CSMEM>>>(
        pZM, pAE, pBE, pIAf, pIBf, nidx, b_tab, pCA, pCB);
    classbw_tf32<<<dim3(DM / 64, LEN / 128, BSZ), 256, CSMEM>>>(
        pZM, pCA, pCB, pIAb, pIBb, pSEL, x, pX1);

    ln_kernel<true><<<M1, 128>>>(pX1, ln2_g, ln2_b, pX2);
    gemm_tf32<2, true ><<<dim3(DFF / GBN, M1 / GBM), 256>>>(pX2, Wf1R, bf1, nullptr, pH, M1, DFF, DM);
    gemm_tf32<4, false><<<dim3(DM / GBN, M1 / GBM), 256>>>(pH, Wf2R, bf2, pX1, out, M1, DM, DFF);
}

// round 6
// speedup vs baseline: 1.8261x; 1.6527x over previous
#include <cuda_runtime.h>
#include <cuda_bf16.h>
#include <math.h>
#include <stdint.h>

#define BSZ  64
#define LEN  256
#define DM   512
#define DFF  2048
#define NEXP 992
#define M1   (BSZ * LEN)
#define NSPLIT 8
#define ZSCALE 0.044194173824159216f   // 1/sqrt(512)

typedef __nv_bfloat16 bf16;

// dense bf16 GEMM tiling: 128x128x16
#define ASTB 12    // A smem stride, b32 units (8 k-pairs + 4 pad) -> perfect bank map
#define BSTB 136   // B packed smem stride, b32 units (128 + 8)

// class GEMM tiling: 128x64x16, dual accumulators
#define AFST 12    // classfw A stride (b32)
#define ABST 9     // classbw A stride (b32)
#define BCST 72    // class B stride (b32) 64+8

// classfw stage layout (b32 words): Aa[1536] Ab[1536] Ba[576] Bb[576]
#define CF_AB 1536
#define CF_B  576
#define CF_STAGE (2 * CF_AB + 2 * CF_B)      // 4224
// classbw stage: Aa[1152] Ab[1152] Ba[576] Bb[576]
#define CB_AB 1152
#define CB_STAGE (2 * CB_AB + 2 * CF_B)      // 3456

// ------------------------- scratch -------------------------
static __device__ bf16  g_X2  [(size_t)M1 * DM];
static __device__ bf16  g_XK  [(size_t)M1 * DM];
static __device__ bf16  g_EA0 [(size_t)M1 * DM];
static __device__ bf16  g_EB0 [(size_t)M1 * DM];
static __device__ bf16  g_AE  [(size_t)M1 * DM];
static __device__ bf16  g_BE  [(size_t)M1 * DM];
static __device__ float g_SEL [(size_t)M1 * DM];
static __device__ float g_X1  [(size_t)M1 * DM];
static __device__ bf16  g_ZM  [(size_t)BSZ * NEXP * LEN];
static __device__ bf16  g_CA  [(size_t)BSZ * NEXP * DM];
static __device__ bf16  g_CB  [(size_t)BSZ * NEXP * DM];
static __device__ bf16  g_H   [(size_t)M1 * DFF];
static __device__ float g_IAf [BSZ * NEXP];
static __device__ float g_IBf [BSZ * NEXP];
static __device__ float g_PA  [BSZ * NSPLIT * LEN];
static __device__ float g_PB  [BSZ * NSPLIT * LEN];
static __device__ float g_IAb [BSZ * LEN];
static __device__ float g_IBb [BSZ * LEN];
static __device__ bf16  g_WH  [3670016];           // bf16 weights
static __device__ bf16  g_QH  [(size_t)NEXP * DM]; // bf16 q_tab

// ------------------------- helpers -------------------------
__device__ __forceinline__ uint32_t f2bf2(float lo, float hi) {
    uint32_t r;
    asm("cvt.rn.bf16x2.f32 %0, %1, %2;" : "=r"(r) : "f"(hi), "f"(lo));
    return r;
}
__device__ __forceinline__ uint32_t bfrelu2(uint32_t x) {
    uint32_t r;
    asm("max.bf16x2 %0, %1, %2;" : "=r"(r) : "r"(x), "r"(0u));
    return r;
}
__device__ __forceinline__ uint32_t bfneg2(uint32_t x) { return x ^ 0x80008000u; }
__device__ __forceinline__ float bflo(uint32_t u) { return __uint_as_float(u << 16); }
__device__ __forceinline__ float bfhi(uint32_t u) { return __uint_as_float(u & 0xffff0000u); }

__device__ __forceinline__ void mma16(float* d, const uint32_t* a, const uint32_t* b) {
    asm volatile(
        "mma.sync.aligned.m16n8k16.row.col.f32.bf16.bf16.f32 "
        "{%0,%1,%2,%3}, {%4,%5,%6,%7}, {%8,%9}, {%0,%1,%2,%3};"
        : "+f"(d[0]), "+f"(d[1]), "+f"(d[2]), "+f"(d[3])
        : "r"(a[0]), "r"(a[1]), "r"(a[2]), "r"(a[3]), "r"(b[0]), "r"(b[1]));
}

// fp32 -> bf16 conversion pass
__global__ void cvt_kernel(const float* __restrict__ s, bf16* __restrict__ d, int n4)
{
    int i = blockIdx.x * blockDim.x + threadIdx.x;
    if (i < n4) {
        float4 v = reinterpret_cast<const float4*>(s)[i];
        uint2 o;
        o.x = f2bf2(v.x, v.y);
        o.y = f2bf2(v.z, v.w);
        reinterpret_cast<uint2*>(d)[i] = o;
    }
}

// ------------------------- LayerNorm (bf16 output) -------------------------
__global__ void ln_kernel(const float* __restrict__ X, const float* __restrict__ G,
                          const float* __restrict__ B, bf16* __restrict__ O)
{
    __shared__ float sred[4];
    int row = blockIdx.x;
    int t = threadIdx.x;
    const float4 v = reinterpret_cast<const float4*>(X + (size_t)row * DM)[t];
    float s = v.x + v.y + v.z + v.w;
    #pragma unroll
    for (int o = 16; o; o >>= 1) s += __shfl_down_sync(0xffffffffu, s, o);
    if ((t & 31) == 0) sred[t >> 5] = s;
    __syncthreads();
    float mu = (sred[0] + sred[1] + sred[2] + sred[3]) * (1.0f / DM);
    __syncthreads();
    float4 d;
    d.x = v.x - mu; d.y = v.y - mu; d.z = v.z - mu; d.w = v.w - mu;
    float ss = d.x * d.x + d.y * d.y + d.z * d.z + d.w * d.w;
    #pragma unroll
    for (int o = 16; o; o >>= 1) ss += __shfl_down_sync(0xffffffffu, ss, o);
    if ((t & 31) == 0) sred[t >> 5] = ss;
    __syncthreads();
    float var = (sred[0] + sred[1] + sred[2] + sred[3]) * (1.0f / DM);
    float rstd = rsqrtf(var + 1e-5f);
    const float4 g4 = reinterpret_cast<const float4*>(G)[t];
    const float4 b4 = reinterpret_cast<const float4*>(B)[t];
    uint2 o;
    o.x = f2bf2(d.x * rstd * g4.x + b4.x, d.y * rstd * g4.y + b4.y);
    o.y = f2bf2(d.z * rstd * g4.z + b4.z, d.w * rstd * g4.w + b4.w);
    reinterpret_cast<uint2*>(O + (size_t)row * DM)[t] = o;
}

// ------------------------- bf16 NN GEMM (128x128x16, m16n8k16, reg-staged) -------------------
// MODE 0: bf16 out = acc+bias;  1: fp32 out = sigmoid;  2: bf16 out = relu;
// MODE 3: bf16 out = Dm(bf16)*sigmoid;  4: fp32 out = Dm(fp32)+acc+bias
template <int MODE>
__global__ void __launch_bounds__(256) gemm_bf16(
    const bf16* __restrict__ A, const bf16* __restrict__ B,
    const float* __restrict__ bias, const void* __restrict__ Dm,
    void* __restrict__ C, int M, int N, int K)
{
    __shared__ uint32_t AsU[2][128 * ASTB];
    __shared__ uint32_t BsU[2][8 * BSTB];
    int tid = threadIdx.x;
    int bm = blockIdx.y * 128, bn = blockIdx.x * 128;
    int warp = tid >> 5, lane = tid & 31;
    int wr = warp >> 1, wc = warp & 1;
    int g = lane >> 2, t4 = lane & 3;

    int arow = tid >> 1, ac8 = (tid & 1) * 8, ac2 = (tid & 1) * 4;
    int bk2 = tid >> 5, bc = (lane) * 4;

    float acc[2][8][4];
    #pragma unroll
    for (int c = 0; c < 2; c++)
        #pragma unroll
        for (int nb = 0; nb < 8; nb++)
            #pragma unroll
            for (int i = 0; i < 4; i++) acc[c][nb][i] = 0.f;

    int KT = K / 16;
    uint4 ra; uint2 rb0, rb1;

    auto loadregs = [&](int k0) {
        ra  = *reinterpret_cast<const uint4*>(A + (size_t)(bm + arow) * K + k0 + ac8);
        rb0 = *reinterpret_cast<const uint2*>(B + (size_t)(k0 + 2 * bk2) * N + bn + bc);
        rb1 = *reinterpret_cast<const uint2*>(B + (size_t)(k0 + 2 * bk2 + 1) * N + bn + bc);
    };
    auto storeregs = [&](int s) {
        *reinterpret_cast<uint4*>(&AsU[s][arow * ASTB + ac2]) = ra;
        uint32_t* bp = &BsU[s][bk2 * BSTB + bc];
        bp[0] = __byte_perm(rb0.x, rb1.x, 0x5410);
        bp[1] = __byte_perm(rb0.x, rb1.x, 0x7632);
        bp[2] = __byte_perm(rb0.y, rb1.y, 0x5410);
        bp[3] = __byte_perm(rb0.y, rb1.y, 0x7632);
    };
    auto compute = [&](int s) {
        uint32_t a[2][4], b[8][2];
        #pragma unroll
        for (int c = 0; c < 2; c++) {
            int row = wr * 32 + c * 16 + g;
            a[c][0] = AsU[s][row * ASTB + t4];
            a[c][1] = AsU[s][(row + 8) * ASTB + t4];
            a[c][2] = AsU[s][row * ASTB + t4 + 4];
            a[c][3] = AsU[s][(row + 8) * ASTB + t4 + 4];
        }
        #pragma unroll
        for (int nb = 0; nb < 8; nb++) {
            int col = wc * 64 + nb * 8 + g;
            b[nb][0] = BsU[s][t4 * BSTB + col];
            b[nb][1] = BsU[s][(t4 + 4) * BSTB + col];
        }
        #pragma unroll
        for (int c = 0; c < 2; c++)
            #pragma unroll
            for (int nb = 0; nb < 8; nb++)
                mma16(acc[c][nb], a[c], b[nb]);
    };

    loadregs(0);
    storeregs(0);
    __syncthreads();
    for (int t = 0; t < KT; t++) {
        if (t + 1 < KT) loadregs((t + 1) * 16);
        compute(t & 1);
        if (t + 1 < KT) storeregs((t + 1) & 1);
        __syncthreads();
    }

    #pragma unroll
    for (int c = 0; c < 2; c++) {
        #pragma unroll
        for (int nb = 0; nb < 8; nb++) {
            int n = bn + wc * 64 + nb * 8 + 2 * t4;
            float2 bi = *reinterpret_cast<const float2*>(bias + n);
            #pragma unroll
            for (int h = 0; h < 2; h++) {
                int m = bm + wr * 32 + c * 16 + g + h * 8;
                size_t off = (size_t)m * N + n;
                float v0 = acc[c][nb][h * 2 + 0] + bi.x;
                float v1 = acc[c][nb][h * 2 + 1] + bi.y;
                if (MODE == 1) {
                    v0 = 1.f / (1.f + expf(-v0)); v1 = 1.f / (1.f + expf(-v1));
                } else if (MODE == 2) {
                    v0 = fmaxf(v0, 0.f); v1 = fmaxf(v1, 0.f);
                } else if (MODE == 3) {
                    uint32_t du = *reinterpret_cast<const uint32_t*>((const bf16*)Dm + off);
                    v0 = bflo(du) / (1.f + expf(-v0));
                    v1 = bfhi(du) / (1.f + expf(-v1));
                } else if (MODE == 4) {
                    float2 d2 = *reinterpret_cast<const float2*>((const float*)Dm + off);
                    v0 += d2.x; v1 += d2.y;
                }
                if (MODE == 1 || MODE == 4) {
                    float2 o = make_float2(v0, v1);
                    *reinterpret_cast<float2*>((float*)C + off) = o;
                } else {
                    *reinterpret_cast<uint32_t*>((bf16*)C + off) = f2bf2(v0, v1);
                }
            }
        }
    }
}

// ------------------------- z GEMM: gather(q_tab) @ XK^T, masked bf16 epilogue -> ZM ----------
__global__ void __launch_bounds__(256) zgemm_bf16(
    const int* __restrict__ nidx, const bf16* __restrict__ qh,
    const bf16* __restrict__ XK, const int* __restrict__ mask,
    bf16* __restrict__ ZM)
{
    __shared__ uint32_t AsU[2][128 * ASTB];
    __shared__ uint32_t BsU[2][8 * BSTB];
    __shared__ int sidx[128];
    int tid = threadIdx.x;
    int b  = blockIdx.z;
    int bm = blockIdx.y * 128;   // expert n
    int bl = blockIdx.x * 128;   // l
    int warp = tid >> 5, lane = tid & 31;
    int wr = warp >> 1, wc = warp & 1;
    int g = lane >> 2, t4 = lane & 3;

    if (tid < 128) {
        int n = bm + tid;
        sidx[tid] = nidx[b * NEXP + (n < NEXP ? n : NEXP - 1)];
    }
    __syncthreads();

    float acc[2][8][4];
    #pragma unroll
    for (int c = 0; c < 2; c++)
        #pragma unroll
        for (int nb = 0; nb < 8; nb++)
            #pragma unroll
            for (int i = 0; i < 4; i++) acc[c][nb][i] = 0.f;

    int arow = tid >> 1, ac8 = (tid & 1) * 8, ac2 = (tid & 1) * 4;
    uint4 ra, rbv;
    auto loadregs = [&](int k0) {
        ra  = *reinterpret_cast<const uint4*>(qh + (size_t)sidx[arow] * DM + k0 + ac8);
        rbv = *reinterpret_cast<const uint4*>(XK + (size_t)(b * LEN + bl + arow) * DM + k0 + ac8);
    };
    auto storeregs = [&](int s) {
        *reinterpret_cast<uint4*>(&AsU[s][arow * ASTB + ac2]) = ra;
        // transpose-pack: word i holds XK[l][k0+ac8+2i .. +2i+1] -> Bp[ac8/2+i][l]
        BsU[s][(ac2 + 0) * BSTB + arow] = rbv.x;
        BsU[s][(ac2 + 1) * BSTB + arow] = rbv.y;
        BsU[s][(ac2 + 2) * BSTB + arow] = rbv.z;
        BsU[s][(ac2 + 3) * BSTB + arow] = rbv.w;
    };
    auto compute = [&](int s) {
        uint32_t a[2][4], bfr[8][2];
        #pragma unroll
        for (int c = 0; c < 2; c++) {
            int row = wr * 32 + c * 16 + g;
            a[c][0] = AsU[s][row * ASTB + t4];
            a[c][1] = AsU[s][(row + 8) * ASTB + t4];
            a[c][2] = AsU[s][row * ASTB + t4 + 4];
            a[c][3] = AsU[s][(row + 8) * ASTB + t4 + 4];
        }
        #pragma unroll
        for (int nb = 0; nb < 8; nb++) {
            int col = wc * 64 + nb * 8 + g;
            bfr[nb][0] = BsU[s][t4 * BSTB + col];
            bfr[nb][1] = BsU[s][(t4 + 4) * BSTB + col];
        }
        #pragma unroll
        for (int c = 0; c < 2; c++)
            #pragma unroll
            for (int nb = 0; nb < 8; nb++)
                mma16(acc[c][nb], a[c], bfr[nb]);
    };

    int KT = DM / 16;
    loadregs(0);
    storeregs(0);
    __syncthreads();
    for (int t = 0; t < KT; t++) {
        if (t + 1 < KT) loadregs((t + 1) * 16);
        compute(t & 1);
        if (t + 1 < KT) storeregs((t + 1) & 1);
        __syncthreads();
    }

    bf16* Zb = ZM + (size_t)b * NEXP * LEN;
    const int* Mb = mask + (size_t)b * NEXP * LEN;
    #pragma unroll
    for (int c = 0; c < 2; c++) {
        #pragma unroll
        for (int nb = 0; nb < 8; nb++) {
            int l = bl + wc * 64 + nb * 8 + 2 * t4;
            #pragma unroll
            for (int h = 0; h < 2; h++) {
                int n = bm + wr * 32 + c * 16 + g + h * 8;
                if (n < NEXP) {
                    size_t off = (size_t)n * LEN + l;
                    int2 m2 = *reinterpret_cast<const int2*>(Mb + off);
                    float v0 = m2.x ? acc[c][nb][h * 2 + 0] * ZSCALE : 0.f;
                    float v1 = m2.y ? acc[c][nb][h * 2 + 1] * ZSCALE : 0.f;
                    *reinterpret_cast<uint32_t*>(Zb + off) = f2bf2(v0, v1);
                }
            }
        }
    }
}

// ------------------------- fused sums on bf16 ZM ---------------------------------------------
__global__ void __launch_bounds__(256) sums_fused(
    const bf16* __restrict__ ZM,
    float* __restrict__ invA, float* __restrict__ invB,
    float* __restrict__ psA, float* __restrict__ psB)
{
    __shared__ float colA[8][LEN];
    __shared__ float colB[8][LEN];
    int b = blockIdx.x, s = blockIdx.y;
    int warp = threadIdx.x >> 5, lane = threadIdx.x & 31;
    int n0 = s * (NEXP / NSPLIT);

    float ca0[4] = {}, ca1[4] = {}, cb0[4] = {}, cb1[4] = {};

    for (int r = warp; r < NEXP / NSPLIT; r += 8) {
        int n = n0 + r;
        const uint32_t* zr = reinterpret_cast<const uint32_t*>(ZM + ((size_t)b * NEXP + n) * LEN);
        float sa = 0.f, sb = 0.f;
        #pragma unroll
        for (int c = 0; c < 4; c++) {
            uint32_t u = zr[c * 32 + lane];
            float lo = bflo(u), hi = bfhi(u);
            float fa0 = fmaxf(lo, 0.f), fa1 = fmaxf(hi, 0.f);
            float fb0 = fmaxf(-lo, 0.f), fb1 = fmaxf(-hi, 0.f);
            sa += fa0 + fa1; sb += fb0 + fb1;
            ca0[c] += fa0; ca1[c] += fa1;
            cb0[c] += fb0; cb1[c] += fb1;
        }
        #pragma unroll
        for (int o = 16; o; o >>= 1) {
            sa += __shfl_down_sync(0xffffffffu, sa, o);
            sb += __shfl_down_sync(0xffffffffu, sb, o);
        }
        if (!lane) {
            invA[b * NEXP + n] = 1.f / (sa + 1e-9f);
            invB[b * NEXP + n] = 1.f / (sb + 1e-9f);
        }
    }
    #pragma unroll
    for (int c = 0; c < 4; c++) {
        colA[warp][c * 64 + 2 * lane]     = ca0[c];
        colA[warp][c * 64 + 2 * lane + 1] = ca1[c];
        colB[warp][c * 64 + 2 * lane]     = cb0[c];
        colB[warp][c * 64 + 2 * lane + 1] = cb1[c];
    }
    __syncthreads();
    int l = threadIdx.x;
    float sa = 0.f, sb = 0.f;
    #pragma unroll
    for (int w = 0; w < 8; w++) { sa += colA[w][l]; sb += colB[w][l]; }
    psA[((size_t)b * NSPLIT + s) * LEN + l] = sa;
    psB[((size_t)b * NSPLIT + s) * LEN + l] = sb;
}

__global__ void bw_final(const float* __restrict__ psA, const float* __restrict__ psB,
                         float* __restrict__ invA, float* __restrict__ invB)
{
    int b = blockIdx.x, l = threadIdx.x;
    float sa = 0.f, sb = 0.f;
    for (int s = 0; s < NSPLIT; s++) {
        sa += psA[((size_t)b * NSPLIT + s) * LEN + l];
        sb += psB[((size_t)b * NSPLIT + s) * LEN + l];
    }
    invA[b * LEN + l] = 1.f / (sa + 1e-9f);
    invB[b * LEN + l] = 1.f / (sb + 1e-9f);
}

// ------------------------- forward class GEMM, bf16 dual (128x64) ----------------------------
__global__ void __launch_bounds__(256) classfw_bf16(
    const bf16* __restrict__ ZM,
    const bf16* __restrict__ AE, const bf16* __restrict__ BE,
    const float* __restrict__ invA, const float* __restrict__ invB,
    const int* __restrict__ nidx, const float* __restrict__ btab,
    bf16* __restrict__ CA, bf16* __restrict__ CB)
{
    __shared__ uint32_t sm[2][CF_STAGE];
    int tid = threadIdx.x;
    int b  = blockIdx.z;
    int bm = blockIdx.y * 128;   // expert n
    int bn = blockIdx.x * 64;    // d
    int warp = tid >> 5, lane = tid & 31;
    int wr = warp >> 1, wc = warp & 1;
    int g = lane >> 2, t4 = lane & 3;

    float acca[2][4][4] = {}, accb[2][4][4] = {};

    int anr = tid >> 1, alc8 = (tid & 1) * 8, alc2 = (tid & 1) * 4;
    int bl2 = tid >> 5, bdc = lane * 2;
    uint4 za; uint32_t rE0, rE1, rB0, rB1;

    auto loadregs = [&](int k0) {
        int n = bm + anr; if (n >= NEXP) n = NEXP - 1;
        za = *reinterpret_cast<const uint4*>(ZM + ((size_t)b * NEXP + n) * LEN + k0 + alc8);
        size_t e0 = ((size_t)b * LEN + k0 + 2 * bl2) * DM + bn + bdc;
        size_t e1 = e0 + DM;
        rE0 = *reinterpret_cast<const uint32_t*>(AE + e0);
        rE1 = *reinterpret_cast<const uint32_t*>(AE + e1);
        rB0 = *reinterpret_cast<const uint32_t*>(BE + e0);
        rB1 = *reinterpret_cast<const uint32_t*>(BE + e1);
    };
    auto storeregs = [&](int s) {
        uint32_t* Aa = &sm[s][0];
        uint32_t* Ab = &sm[s][CF_AB];
        uint32_t* Ba = &sm[s][2 * CF_AB];
        uint32_t* Bb = &sm[s][2 * CF_AB + CF_B];
        uint4 ua, ub;
        ua.x = bfrelu2(za.x); ub.x = bfrelu2(bfneg2(za.x));
        ua.y = bfrelu2(za.y); ub.y = bfrelu2(bfneg2(za.y));
        ua.z = bfrelu2(za.z); ub.z = bfrelu2(bfneg2(za.z));
        ua.w = bfrelu2(za.w); ub.w = bfrelu2(bfneg2(za.w));
        *reinterpret_cast<uint4*>(&Aa[anr * AFST + alc2]) = ua;
        *reinterpret_cast<uint4*>(&Ab[anr * AFST + alc2]) = ub;
        Ba[bl2 * BCST + bdc]     = __byte_perm(rE0, rE1, 0x5410);
        Ba[bl2 * BCST + bdc + 1] = __byte_perm(rE0, rE1, 0x7632);
        Bb[bl2 * BCST + bdc]     = __byte_perm(rB0, rB1, 0x5410);
        Bb[bl2 * BCST + bdc + 1] = __byte_perm(rB0, rB1, 0x7632);
    };
    auto compute = [&](int s) {
        const uint32_t* Aa = &sm[s][0];
        const uint32_t* Ab = &sm[s][CF_AB];
        const uint32_t* Ba = &sm[s][2 * CF_AB];
        const uint32_t* Bb = &sm[s][2 * CF_AB + CF_B];
        uint32_t afa[2][4], afb[2][4], bfa[4][2], bfb[4][2];
        #pragma unroll
        for (int c = 0; c < 2; c++) {
            int row = wr * 32 + c * 16 + g;
            afa[c][0] = Aa[row * AFST + t4];
            afa[c][1] = Aa[(row + 8) * AFST + t4];
            afa[c][2] = Aa[row * AFST + t4 + 4];
            afa[c][3] = Aa[(row + 8) * AFST + t4 + 4];
            afb[c][0] = Ab[row * AFST + t4];
            afb[c][1] = Ab[(row + 8) * AFST + t4];
            afb[c][2] = Ab[row * AFST + t4 + 4];
            afb[c][3] = Ab[(row + 8) * AFST + t4 + 4];
        }
        #pragma unroll
        for (int nb = 0; nb < 4; nb++) {
            int col = wc * 32 + nb * 8 + g;
            bfa[nb][0] = Ba[t4 * BCST + col];
            bfa[nb][1] = Ba[(t4 + 4) * BCST + col];
            bfb[nb][0] = Bb[t4 * BCST + col];
            bfb[nb][1] = Bb[(t4 + 4) * BCST + col];
        }
        #pragma unroll
        for (int c = 0; c < 2; c++)
            #pragma unroll
            for (int nb = 0; nb < 4; nb++) {
                mma16(acca[c][nb], afa[c], bfa[nb]);
                mma16(accb[c][nb], afb[c], bfb[nb]);
            }
    };

    loadregs(0);
    storeregs(0);
    __syncthreads();
    const int KT = LEN / 16;   // 16
    for (int t = 0; t < KT; t++) {
        if (t + 1 < KT) loadregs((t + 1) * 16);
        compute(t & 1);
        if (t + 1 < KT) storeregs((t + 1) & 1);
        __syncthreads();
    }

    #pragma unroll
    for (int c = 0; c < 2; c++) {
        #pragma unroll
        for (int h = 0; h < 2; h++) {
            int n = bm + wr * 32 + c * 16 + g + h * 8;
            if (n >= NEXP) continue;
            float ia = invA[b * NEXP + n];
            float ib = invB[b * NEXP + n];
            int qi = nidx[b * NEXP + n];
            #pragma unroll
            for (int nb = 0; nb < 4; nb++) {
                int d0 = bn + wc * 32 + nb * 8 + 2 * t4;
                float2 bi = *reinterpret_cast<const float2*>(btab + (size_t)qi * DM + d0);
                size_t off = ((size_t)b * NEXP + n) * DM + d0;
                *reinterpret_cast<uint32_t*>(CA + off) =
                    f2bf2(acca[c][nb][h * 2 + 0] * ia + bi.x,
                          acca[c][nb][h * 2 + 1] * ia + bi.y);
                *reinterpret_cast<uint32_t*>(CB + off) =
                    f2bf2(accb[c][nb][h * 2 + 0] * ib + bi.x,
                          accb[c][nb][h * 2 + 1] * ib + bi.y);
            }
        }
    }
}

// ------------------------- backward class GEMM, bf16 dual (128x64), blend+residual -----------
__global__ void __launch_bounds__(256) classbw_bf16(
    const bf16* __restrict__ ZM,
    const bf16* __restrict__ CA, const bf16* __restrict__ CB,
    const float* __restrict__ invA, const float* __restrict__ invB,
    const float* __restrict__ SELp, const float* __restrict__ X,
    float* __restrict__ X1)
{
    __shared__ uint32_t sm[2][CB_STAGE];
    int tid = threadIdx.x;
    int b  = blockIdx.z;
    int bl = blockIdx.y * 128;   // l
    int bn = blockIdx.x * 64;    // d
    int warp = tid >> 5, lane = tid & 31;
    int wr = warp >> 1, wc = warp & 1;
    int g = lane >> 2, t4 = lane & 3;

    float acca[2][4][4] = {}, accb[2][4][4] = {};

    int n2 = tid >> 5, l4 = lane * 4;
    int bdc = lane * 2;
    uint2 ze, zo; uint32_t rC0, rC1, rD0, rD1;

    auto loadregs = [&](int k0) {
        size_t z0 = ((size_t)b * NEXP + k0 + 2 * n2) * LEN + bl + l4;
        ze = *reinterpret_cast<const uint2*>(ZM + z0);
        zo = *reinterpret_cast<const uint2*>(ZM + z0 + LEN);
        size_t c0 = ((size_t)b * NEXP + k0 + 2 * n2) * DM + bn + bdc;
        size_t c1 = c0 + DM;
        rC0 = *reinterpret_cast<const uint32_t*>(CA + c0);
        rC1 = *reinterpret_cast<const uint32_t*>(CA + c1);
        rD0 = *reinterpret_cast<const uint32_t*>(CB + c0);
        rD1 = *reinterpret_cast<const uint32_t*>(CB + c1);
    };
    auto storeregs = [&](int s) {
        uint32_t* Aa = &sm[s][0];
        uint32_t* Ab = &sm[s][CB_AB];
        uint32_t* Ba = &sm[s][2 * CB_AB];
        uint32_t* Bb = &sm[s][2 * CB_AB + CF_B];
        uint32_t p[4];
        p[0] = __byte_perm(ze.x, zo.x, 0x5410);
        p[1] = __byte_perm(ze.x, zo.x, 0x7632);
        p[2] = __byte_perm(ze.y, zo.y, 0x5410);
        p[3] = __byte_perm(ze.y, zo.y, 0x7632);
        #pragma unroll
        for (int i = 0; i < 4; i++) {
            Aa[(l4 + i) * ABST + n2] = bfrelu2(p[i]);
            Ab[(l4 + i) * ABST + n2] = bfrelu2(bfneg2(p[i]));
        }
        Ba[n2 * BCST + bdc]     = __byte_perm(rC0, rC1, 0x5410);
        Ba[n2 * BCST + bdc + 1] = __byte_perm(rC0, rC1, 0x7632);
        Bb[n2 * BCST + bdc]     = __byte_perm(rD0, rD1, 0x5410);
        Bb[n2 * BCST + bdc + 1] = __byte_perm(rD0, rD1, 0x7632);
    };
    auto compute = [&](int s) {
        const uint32_t* Aa = &sm[s][0];
        const uint32_t* Ab = &sm[s][CB_AB];
        const uint32_t* Ba = &sm[s][2 * CB_AB];
        const uint32_t* Bb = &sm[s][2 * CB_AB + CF_B];
        uint32_t afa[2][4], afb[2][4], bfa[4][2], bfb[4][2];
        #pragma unroll
        for (int c = 0; c < 2; c++) {
            int row = wr * 32 + c * 16 + g;
            afa[c][0] = Aa[row * ABST + t4];
            afa[c][1] = Aa[(row + 8) * ABST + t4];
            afa[c][2] = Aa[row * ABST + t4 + 4];
            afa[c][3] = Aa[(row + 8) * ABST + t4 + 4];
            afb[c][0] = Ab[row * ABST + t4];
            afb[c][1] = Ab[(row + 8) * ABST + t4];
            afb[c][2] = Ab[row * ABST + t4 + 4];
            afb[c][3] = Ab[(row + 8) * ABST + t4 + 4];
        }
        #pragma unroll
        for (int nb = 0; nb < 4; nb++) {
            int col = wc * 32 + nb * 8 + g;
            bfa[nb][0] = Ba[t4 * BCST + col];
            bfa[nb][1] = Ba[(t4 + 4) * BCST + col];
            bfb[nb][0] = Bb[t4 * BCST + col];
            bfb[nb][1] = Bb[(t4 + 4) * BCST + col];
        }
        #pragma unroll
        for (int c = 0; c < 2; c++)
            #pragma unroll
            for (int nb = 0; nb < 4; nb++) {
                mma16(acca[c][nb], afa[c], bfa[nb]);
                mma16(accb[c][nb], afb[c], bfb[nb]);
            }
    };

    loadregs(0);
    storeregs(0);
    __syncthreads();
    const int KT = NEXP / 16;    // 62
    for (int t = 0; t < KT; t++) {
        if (t + 1 < KT) loadregs((t + 1) * 16);
        compute(t & 1);
        if (t + 1 < KT) storeregs((t + 1) & 1);
        __syncthreads();
    }

    #pragma unroll
    for (int c = 0; c < 2; c++) {
        #pragma unroll
        for (int h = 0; h < 2; h++) {
            int l = bl + wr * 32 + c * 16 + g + h * 8;
            float ia = invA[b * LEN + l];
            float ib = invB[b * LEN + l];
            #pragma unroll
            for (int nb = 0; nb < 4; nb++) {
                int d0 = bn + wc * 32 + nb * 8 + 2 * t4;
                size_t off = ((size_t)b * LEN + l) * DM + d0;
                float2 s2 = *reinterpret_cast<const float2*>(SELp + off);
                float2 x2 = *reinterpret_cast<const float2*>(X + off);
                float2 o;
                o.x = x2.x + s2.x * (acca[c][nb][h * 2 + 0] * ia)
                           + (1.f - s2.x) * (accb[c][nb][h * 2 + 0] * ib);
                o.y = x2.y + s2.y * (acca[c][nb][h * 2 + 1] * ia)
                           + (1.f - s2.y) * (accb[c][nb][h * 2 + 1] * ib);
                *reinterpret_cast<float2*>(X1 + off) = o;
            }
        }
    }
}

// ------------------------- launch -------------------------
extern "C" void kernel_launch(void* const* d_in, const int* in_sizes, int n_in,
                              void* d_out, int out_size)
{
    const float* x     = (const float*)d_in[0];
    const int*   nidx  = (const int*)d_in[1];
    const int*   mask  = (const int*)d_in[2];
    const float* ln1_g = (const float*)d_in[3];
    const float* ln1_b = (const float*)d_in[4];
    const float* ln2_g = (const float*)d_in[5];
    const float* ln2_b = (const float*)d_in[6];
    const float* q_tab = (const float*)d_in[7];
    const float* b_tab = (const float*)d_in[8];
    const float* Wk  = (const float*)d_in[9];  const float* bk   = (const float*)d_in[10];
    const float* Wa  = (const float*)d_in[11]; const float* ba   = (const float*)d_in[12];
    const float* Wa1 = (const float*)d_in[13]; const float* ba1  = (const float*)d_in[14];
    const float* Wb  = (const float*)d_in[15]; const float* bb   = (const float*)d_in[16];
    const float* Wb1 = (const float*)d_in[17]; const float* bb1  = (const float*)d_in[18];
    const float* Ws  = (const float*)d_in[19]; const float* bsel = (const float*)d_in[20];
    const float* Wf1 = (const float*)d_in[21]; const float* bf1  = (const float*)d_in[22];
    const float* Wf2 = (const float*)d_in[23]; const float* bf2  = (const float*)d_in[24];
    float* out = (float*)d_out;

    bf16 *pX2, *pXK, *pEA0, *pEB0, *pAE, *pBE, *pZM, *pCA, *pCB, *pH, *pWH, *pQH;
    float *pSEL, *pX1, *pIAf, *pIBf, *pPA, *pPB, *pIAb, *pIBb;
    cudaGetSymbolAddress((void**)&pX2, g_X2);
    cudaGetSymbolAddress((void**)&pXK, g_XK);
    cudaGetSymbolAddress((void**)&pEA0, g_EA0);
    cudaGetSymbolAddress((void**)&pEB0, g_EB0);
    cudaGetSymbolAddress((void**)&pAE, g_AE);
    cudaGetSymbolAddress((void**)&pBE, g_BE);
    cudaGetSymbolAddress((void**)&pSEL, g_SEL);
    cudaGetSymbolAddress((void**)&pX1, g_X1);
    cudaGetSymbolAddress((void**)&pZM, g_ZM);
    cudaGetSymbolAddress((void**)&pCA, g_CA);
    cudaGetSymbolAddress((void**)&pCB, g_CB);
    cudaGetSymbolAddress((void**)&pH, g_H);
    cudaGetSymbolAddress((void**)&pIAf, g_IAf);
    cudaGetSymbolAddress((void**)&pIBf, g_IBf);
    cudaGetSymbolAddress((void**)&pPA, g_PA);
    cudaGetSymbolAddress((void**)&pPB, g_PB);
    cudaGetSymbolAddress((void**)&pIAb, g_IAb);
    cudaGetSymbolAddress((void**)&pIBb, g_IBb);
    cudaGetSymbolAddress((void**)&pWH, g_WH);
    cudaGetSymbolAddress((void**)&pQH, g_QH);

    bf16* WkH  = pWH;
    bf16* WaH  = pWH + 262144;
    bf16* WbH  = pWH + 524288;
    bf16* WsH  = pWH + 786432;
    bf16* Wa1H = pWH + 1048576;
    bf16* Wb1H = pWH + 1310720;
    bf16* Wf1H = pWH + 1572864;
    bf16* Wf2H = pWH + 2621440;

    dim3 gA(DM / 128, M1 / 128);

    // Launch order arranged so ncu `-s 5 -c 1` profiles zgemm_bf16 (launch index 5).
    cvt_kernel<<<256, 256>>>(Wk, WkH, 65536);                                   // 0
    ln_kernel<<<M1, 128>>>(x, ln1_g, ln1_b, pX2);                               // 1
    gemm_bf16<0><<<gA, 256>>>(pX2, WkH, bk, nullptr, pXK, M1, DM, DM);          // 2
    cvt_kernel<<<496, 256>>>(q_tab, pQH, 126976);                               // 3
    cvt_kernel<<<256, 256>>>(Wa, WaH, 65536);                                   // 4
    zgemm_bf16<<<dim3(LEN / 128, (NEXP + 127) / 128, BSZ), 256>>>(              // 5 <-- profiled
        nidx, pQH, pXK, mask, pZM);

    cvt_kernel<<<256, 256>>>(Wb,  WbH,  65536);
    cvt_kernel<<<256, 256>>>(Ws,  WsH,  65536);
    cvt_kernel<<<256, 256>>>(Wa1, Wa1H, 65536);
    cvt_kernel<<<256, 256>>>(Wb1, Wb1H, 65536);
    cvt_kernel<<<1024, 256>>>(Wf1, Wf1H, 262144);
    cvt_kernel<<<1024, 256>>>(Wf2, Wf2H, 262144);

    gemm_bf16<0><<<gA, 256>>>(pX2, WaH, ba, nullptr, pEA0, M1, DM, DM);
    gemm_bf16<0><<<gA, 256>>>(pX2, WbH, bb, nullptr, pEB0, M1, DM, DM);
    gemm_bf16<1><<<gA, 256>>>(pX2, WsH, bsel, nullptr, pSEL, M1, DM, DM);
    gemm_bf16<3><<<gA, 256>>>(pEA0, Wa1H, ba1, pEA0, pAE, M1, DM, DM);
    gemm_bf16<3><<<gA, 256>>>(pEB0, Wb1H, bb1, pEB0, pBE, M1, DM, DM);

    sums_fused<<<dim3(BSZ, NSPLIT), 256>>>(pZM, pIAf, pIBf, pPA, pPB);
    bw_final<<<BSZ, LEN>>>(pPA, pPB, pIAb, pIBb);

    classfw_bf16<<<dim3(DM / 64, (NEXP + 127) / 128, BSZ), 256>>>(
        pZM, pAE, pBE, pIAf, pIBf, nidx, b_tab, pCA, pCB);
    classbw_bf16<<<dim3(DM / 64, LEN / 128, BSZ), 256>>>(
        pZM, pCA, pCB, pIAb, pIBb, pSEL, x, pX1);

    ln_kernel<<<M1, 128>>>(pX1, ln2_g, ln2_b, pX2);
    gemm_bf16<2><<<dim3(DFF / 128, M1 / 128), 256>>>(pX2, Wf1H, bf1, nullptr, pH, M1, DFF, DM);
    gemm_bf16<4><<<dim3(DM / 128, M1 / 128), 256>>>(pH, Wf2H, bf2, pX1, out, M1, DM, DFF);
}

// round 8
// speedup vs baseline: 1.9544x; 1.0703x over previous
#include <cuda_runtime.h>
#include <cuda_bf16.h>
#include <math.h>
#include <stdint.h>

#define BSZ  64
#define LEN  256
#define DM   512
#define DFF  2048
#define NEXP 992
#define M1   (BSZ * LEN)
#define NSPLIT 8
#define ZSCALE 0.044194173824159216f   // 1/sqrt(512)

typedef __nv_bfloat16 bf16;

// ---- dense GEMM (K-tile 32) smem strides, b32 units ----
#define AST2 20    // 16 k-pair words + 4 pad (conflict-free fragment loads)
#define BST2 136   // 128 + 8

// ---- z GEMM tiling (K-tile 16, unchanged from R6) ----
#define ASTB 12
#define BSTB 136

// ---- class GEMM tiling (unchanged from R6) ----
#define AFST 12
#define ABST 9
#define BCST 72
#define CF_AB 1536
#define CF_B  576
#define CF_STAGE (2 * CF_AB + 2 * CF_B)
#define CB_AB 1152
#define CB_STAGE (2 * CB_AB + 2 * CF_B)

// ------------------------- scratch -------------------------
static __device__ bf16  g_X2  [(size_t)M1 * DM];
static __device__ bf16  g_XK  [(size_t)M1 * DM];
static __device__ bf16  g_EA0 [(size_t)M1 * DM];
static __device__ bf16  g_EB0 [(size_t)M1 * DM];
static __device__ bf16  g_AE  [(size_t)M1 * DM];
static __device__ bf16  g_BE  [(size_t)M1 * DM];
static __device__ float g_SEL [(size_t)M1 * DM];
static __device__ float g_X1  [(size_t)M1 * DM];
static __device__ bf16  g_ZM  [(size_t)BSZ * NEXP * LEN];
static __device__ bf16  g_CA  [(size_t)BSZ * NEXP * DM];
static __device__ bf16  g_CB  [(size_t)BSZ * NEXP * DM];
static __device__ bf16  g_H   [(size_t)M1 * DFF];
static __device__ float g_IAf [BSZ * NEXP];
static __device__ float g_IBf [BSZ * NEXP];
static __device__ float g_PA  [BSZ * NSPLIT * LEN];
static __device__ float g_PB  [BSZ * NSPLIT * LEN];
static __device__ float g_IAb [BSZ * LEN];
static __device__ float g_IBb [BSZ * LEN];
static __device__ bf16  g_WH  [3670016];           // bf16 weights [K,N]
static __device__ bf16  g_QH  [(size_t)NEXP * DM]; // bf16 q_tab

// ------------------------- helpers -------------------------
__device__ __forceinline__ uint32_t f2bf2(float lo, float hi) {
    uint32_t r;
    asm("cvt.rn.bf16x2.f32 %0, %1, %2;" : "=r"(r) : "f"(hi), "f"(lo));
    return r;
}
__device__ __forceinline__ uint32_t bfrelu2(uint32_t x) {
    uint32_t r;
    asm("max.bf16x2 %0, %1, %2;" : "=r"(r) : "r"(x), "r"(0u));
    return r;
}
__device__ __forceinline__ uint32_t bfneg2(uint32_t x) { return x ^ 0x80008000u; }
__device__ __forceinline__ float bflo(uint32_t u) { return __uint_as_float(u << 16); }
__device__ __forceinline__ float bfhi(uint32_t u) { return __uint_as_float(u & 0xffff0000u); }

__device__ __forceinline__ void mma16(float* d, const uint32_t* a, const uint32_t* b) {
    asm volatile(
        "mma.sync.aligned.m16n8k16.row.col.f32.bf16.bf16.f32 "
        "{%0,%1,%2,%3}, {%4,%5,%6,%7}, {%8,%9}, {%0,%1,%2,%3};"
        : "+f"(d[0]), "+f"(d[1]), "+f"(d[2]), "+f"(d[3])
        : "r"(a[0]), "r"(a[1]), "r"(a[2]), "r"(a[3]), "r"(b[0]), "r"(b[1]));
}

// ------------------------- fused fp32->bf16 conversion for all weights -----------------------
struct CvtArgs {
    const float* s[9];
    bf16* d[9];
    int cum[10];   // cumulative float4 counts
};
__global__ void cvt_all(CvtArgs a)
{
    int i = blockIdx.x * blockDim.x + threadIdx.x;
    if (i >= a.cum[9]) return;
    int t = 0;
    #pragma unroll
    for (int j = 1; j < 9; j++) t += (i >= a.cum[j]);
    int off = i - a.cum[t];
    float4 v = reinterpret_cast<const float4*>(a.s[t])[off];
    uint2 o;
    o.x = f2bf2(v.x, v.y);
    o.y = f2bf2(v.z, v.w);
    reinterpret_cast<uint2*>(a.d[t])[off] = o;
}

// ------------------------- LayerNorm (bf16 output) -------------------------
__global__ void ln_kernel(const float* __restrict__ X, const float* __restrict__ G,
                          const float* __restrict__ B, bf16* __restrict__ O)
{
    __shared__ float sred[4];
    int row = blockIdx.x;
    int t = threadIdx.x;
    const float4 v = reinterpret_cast<const float4*>(X + (size_t)row * DM)[t];
    float s = v.x + v.y + v.z + v.w;
    #pragma unroll
    for (int o = 16; o; o >>= 1) s += __shfl_down_sync(0xffffffffu, s, o);
    if ((t & 31) == 0) sred[t >> 5] = s;
    __syncthreads();
    float mu = (sred[0] + sred[1] + sred[2] + sred[3]) * (1.0f / DM);
    __syncthreads();
    float4 d;
    d.x = v.x - mu; d.y = v.y - mu; d.z = v.z - mu; d.w = v.w - mu;
    float ss = d.x * d.x + d.y * d.y + d.z * d.z + d.w * d.w;
    #pragma unroll
    for (int o = 16; o; o >>= 1) ss += __shfl_down_sync(0xffffffffu, ss, o);
    if ((t & 31) == 0) sred[t >> 5] = ss;
    __syncthreads();
    float var = (sred[0] + sred[1] + sred[2] + sred[3]) * (1.0f / DM);
    float rstd = rsqrtf(var + 1e-5f);
    const float4 g4 = reinterpret_cast<const float4*>(G)[t];
    const float4 b4 = reinterpret_cast<const float4*>(B)[t];
    uint2 o;
    o.x = f2bf2(d.x * rstd * g4.x + b4.x, d.y * rstd * g4.y + b4.y);
    o.y = f2bf2(d.z * rstd * g4.z + b4.z, d.w * rstd * g4.w + b4.w);
    reinterpret_cast<uint2*>(O + (size_t)row * DM)[t] = o;
}

// ------------------------- multi-problem bf16 GEMM (128x128, K-tile 32, z-merged) ------------
// Per-z problem spec. mode: 0 bf16 out; 1 fp32 sigmoid; 2 bf16 relu; 3 bf16 Dm*sigmoid;
// 4 fp32 Dm+acc+bias
struct GArg {
    const bf16* A;
    const bf16* B;     // [K,N] row-major
    const float* bias;
    const void* Dm;
    void* C;
    int mode;
};

__global__ void __launch_bounds__(256) gemm_multi(
    GArg g0, GArg g1, GArg g2, GArg g3, int M, int N, int K)
{
    __shared__ uint32_t AsU[2][128 * AST2];
    __shared__ uint32_t BsU[2][16 * BST2];
    GArg ga = (blockIdx.z == 0) ? g0 : (blockIdx.z == 1) ? g1 : (blockIdx.z == 2) ? g2 : g3;

    int tid = threadIdx.x;
    int bm = blockIdx.y * 128, bn = blockIdx.x * 128;
    int warp = tid >> 5, lane = tid & 31;
    int wr = warp >> 1, wc = warp & 1;
    int g = lane >> 2, t4 = lane & 3;

    int arow = tid >> 1, ah16 = (tid & 1) * 16, ah8 = (tid & 1) * 8;  // A: row, 16-bf16 half
    int bw = tid >> 5, bc = lane * 4;                                  // B: kpair-row group, 4 n-words

    float acc[2][8][4];
    #pragma unroll
    for (int c = 0; c < 2; c++)
        #pragma unroll
        for (int nb = 0; nb < 8; nb++)
            #pragma unroll
            for (int i = 0; i < 4; i++) acc[c][nb][i] = 0.f;

    int KT = K / 32;
    uint4 ra0, ra1;
    uint2 rb[4][2];

    auto loadregs = [&](int k0) {
        const bf16* Ap = ga.A + (size_t)(bm + arow) * K + k0 + ah16;
        ra0 = *reinterpret_cast<const uint4*>(Ap);
        ra1 = *reinterpret_cast<const uint4*>(Ap + 8);
        #pragma unroll
        for (int h = 0; h < 2; h++) {
            int kr = k0 + 2 * (bw + h * 8);
            rb[2 * h + 0][0] = *reinterpret_cast<const uint2*>(ga.B + (size_t)kr * N + bn + bc);
            rb[2 * h + 0][1] = *reinterpret_cast<const uint2*>(ga.B + (size_t)(kr + 1) * N + bn + bc);
            (void)0;
            rb[2 * h + 1][0] = rb[2 * h + 0][0];  // placeholder overwritten below
        }
        // reload properly: two k-pair rows (bw, bw+8), each needs rows 2r and 2r+1
        int krA = k0 + 2 * bw;
        rb[0][0] = *reinterpret_cast<const uint2*>(ga.B + (size_t)krA * N + bn + bc);
        rb[0][1] = *reinterpret_cast<const uint2*>(ga.B + (size_t)(krA + 1) * N + bn + bc);
        int krB = k0 + 2 * (bw + 8);
        rb[1][0] = *reinterpret_cast<const uint2*>(ga.B + (size_t)krB * N + bn + bc);
        rb[1][1] = *reinterpret_cast<const uint2*>(ga.B + (size_t)(krB + 1) * N + bn + bc);
    };
    auto storeregs = [&](int s) {
        uint32_t* ap = &AsU[s][arow * AST2 + ah8];
        *reinterpret_cast<uint4*>(ap) = ra0;
        *reinterpret_cast<uint4*>(ap + 4) = ra1;
        uint32_t* bp0 = &BsU[s][bw * BST2 + bc];
        bp0[0] = __byte_perm(rb[0][0].x, rb[0][1].x, 0x5410);
        bp0[1] = __byte_perm(rb[0][0].x, rb[0][1].x, 0x7632);
        bp0[2] = __byte_perm(rb[0][0].y, rb[0][1].y, 0x5410);
        bp0[3] = __byte_perm(rb[0][0].y, rb[0][1].y, 0x7632);
        uint32_t* bp1 = &BsU[s][(bw + 8) * BST2 + bc];
        bp1[0] = __byte_perm(rb[1][0].x, rb[1][1].x, 0x5410);
        bp1[1] = __byte_perm(rb[1][0].x, rb[1][1].x, 0x7632);
        bp1[2] = __byte_perm(rb[1][0].y, rb[1][1].y, 0x5410);
        bp1[3] = __byte_perm(rb[1][0].y, rb[1][1].y, 0x7632);
    };
    auto compute = [&](int s, int h) {
        uint32_t a[2][4], b[8][2];
        #pragma unroll
        for (int c = 0; c < 2; c++) {
            int row = wr * 32 + c * 16 + g;
            const uint32_t* ap = &AsU[s][row * AST2 + h * 8];
            a[c][0] = ap[t4];
            a[c][1] = ap[8 * AST2 + t4];
            a[c][2] = ap[t4 + 4];
            a[c][3] = ap[8 * AST2 + t4 + 4];
        }
        #pragma unroll
        for (int nb = 0; nb < 8; nb++) {
            int col = wc * 64 + nb * 8 + g;
            b[nb][0] = BsU[s][(h * 8 + t4) * BST2 + col];
            b[nb][1] = BsU[s][(h * 8 + t4 + 4) * BST2 + col];
        }
        #pragma unroll
        for (int c = 0; c < 2; c++)
            #pragma unroll
            for (int nb = 0; nb < 8; nb++)
                mma16(acc[c][nb], a[c], b[nb]);
    };

    loadregs(0);
    storeregs(0);
    __syncthreads();
    for (int t = 0; t < KT; t++) {
        if (t + 1 < KT) loadregs((t + 1) * 32);
        compute(t & 1, 0);
        compute(t & 1, 1);
        if (t + 1 < KT) storeregs((t + 1) & 1);
        __syncthreads();
    }

    int mode = ga.mode;
    #pragma unroll
    for (int c = 0; c < 2; c++) {
        #pragma unroll
        for (int nb = 0; nb < 8; nb++) {
            int n = bn + wc * 64 + nb * 8 + 2 * t4;
            float2 bi = *reinterpret_cast<const float2*>(ga.bias + n);
            #pragma unroll
            for (int h = 0; h < 2; h++) {
                int m = bm + wr * 32 + c * 16 + g + h * 8;
                size_t off = (size_t)m * N + n;
                float v0 = acc[c][nb][h * 2 + 0] + bi.x;
                float v1 = acc[c][nb][h * 2 + 1] + bi.y;
                if (mode == 1) {
                    v0 = 1.f / (1.f + expf(-v0)); v1 = 1.f / (1.f + expf(-v1));
                    *reinterpret_cast<float2*>((float*)ga.C + off) = make_float2(v0, v1);
                } else if (mode == 4) {
                    float2 d2 = *reinterpret_cast<const float2*>((const float*)ga.Dm + off);
                    *reinterpret_cast<float2*>((float*)ga.C + off) = make_float2(v0 + d2.x, v1 + d2.y);
                } else {
                    if (mode == 2) {
                        v0 = fmaxf(v0, 0.f); v1 = fmaxf(v1, 0.f);
                    } else if (mode == 3) {
                        uint32_t du = *reinterpret_cast<const uint32_t*>((const bf16*)ga.Dm + off);
                        v0 = bflo(du) / (1.f + expf(-v0));
                        v1 = bfhi(du) / (1.f + expf(-v1));
                    }
                    *reinterpret_cast<uint32_t*>((bf16*)ga.C + off) = f2bf2(v0, v1);
                }
            }
        }
    }
}

// ------------------------- z GEMM (mma.sync, unchanged from R6) ------------------------------
__global__ void __launch_bounds__(256) zgemm_bf16(
    const int* __restrict__ nidx, const bf16* __restrict__ qh,
    const bf16* __restrict__ XK, const int* __restrict__ mask,
    bf16* __restrict__ ZM)
{
    __shared__ uint32_t AsU[2][128 * ASTB];
    __shared__ uint32_t BsU[2][8 * BSTB];
    __shared__ int sidx[128];
    int tid = threadIdx.x;
    int b  = blockIdx.z;
    int bm = blockIdx.y * 128;
    int bl = blockIdx.x * 128;
    int warp = tid >> 5, lane = tid & 31;
    int wr = warp >> 1, wc = warp & 1;
    int g = lane >> 2, t4 = lane & 3;

    if (tid < 128) {
        int n = bm + tid;
        sidx[tid] = nidx[b * NEXP + (n < NEXP ? n : NEXP - 1)];
    }
    __syncthreads();

    float acc[2][8][4];
    #pragma unroll
    for (int c = 0; c < 2; c++)
        #pragma unroll
        for (int nb = 0; nb < 8; nb++)
            #pragma unroll
            for (int i = 0; i < 4; i++) acc[c][nb][i] = 0.f;

    int arow = tid >> 1, ac8 = (tid & 1) * 8, ac2 = (tid & 1) * 4;
    uint4 ra, rbv;
    auto loadregs = [&](int k0) {
        ra  = *reinterpret_cast<const uint4*>(qh + (size_t)sidx[arow] * DM + k0 + ac8);
        rbv = *reinterpret_cast<const uint4*>(XK + (size_t)(b * LEN + bl + arow) * DM + k0 + ac8);
    };
    auto storeregs = [&](int s) {
        *reinterpret_cast<uint4*>(&AsU[s][arow * ASTB + ac2]) = ra;
        BsU[s][(ac2 + 0) * BSTB + arow] = rbv.x;
        BsU[s][(ac2 + 1) * BSTB + arow] = rbv.y;
        BsU[s][(ac2 + 2) * BSTB + arow] = rbv.z;
        BsU[s][(ac2 + 3) * BSTB + arow] = rbv.w;
    };
    auto compute = [&](int s) {
        uint32_t a[2][4], bfr[8][2];
        #pragma unroll
        for (int c = 0; c < 2; c++) {
            int row = wr * 32 + c * 16 + g;
            a[c][0] = AsU[s][row * ASTB + t4];
            a[c][1] = AsU[s][(row + 8) * ASTB + t4];
            a[c][2] = AsU[s][row * ASTB + t4 + 4];
            a[c][3] = AsU[s][(row + 8) * ASTB + t4 + 4];
        }
        #pragma unroll
        for (int nb = 0; nb < 8; nb++) {
            int col = wc * 64 + nb * 8 + g;
            bfr[nb][0] = BsU[s][t4 * BSTB + col];
            bfr[nb][1] = BsU[s][(t4 + 4) * BSTB + col];
        }
        #pragma unroll
        for (int c = 0; c < 2; c++)
            #pragma unroll
            for (int nb = 0; nb < 8; nb++)
                mma16(acc[c][nb], a[c], bfr[nb]);
    };

    int KT = DM / 16;
    loadregs(0);
    storeregs(0);
    __syncthreads();
    for (int t = 0; t < KT; t++) {
        if (t + 1 < KT) loadregs((t + 1) * 16);
        compute(t & 1);
        if (t + 1 < KT) storeregs((t + 1) & 1);
        __syncthreads();
    }

    bf16* Zb = ZM + (size_t)b * NEXP * LEN;
    const int* Mb = mask + (size_t)b * NEXP * LEN;
    #pragma unroll
    for (int c = 0; c < 2; c++) {
        #pragma unroll
        for (int nb = 0; nb < 8; nb++) {
            int l = bl + wc * 64 + nb * 8 + 2 * t4;
            #pragma unroll
            for (int h = 0; h < 2; h++) {
                int n = bm + wr * 32 + c * 16 + g + h * 8;
                if (n < NEXP) {
                    size_t off = (size_t)n * LEN + l;
                    int2 m2 = *reinterpret_cast<const int2*>(Mb + off);
                    float v0 = m2.x ? acc[c][nb][h * 2 + 0] * ZSCALE : 0.f;
                    float v1 = m2.y ? acc[c][nb][h * 2 + 1] * ZSCALE : 0.f;
                    *reinterpret_cast<uint32_t*>(Zb + off) = f2bf2(v0, v1);
                }
            }
        }
    }
}

// ------------------------- fused sums on bf16 ZM ---------------------------------------------
__global__ void __launch_bounds__(256) sums_fused(
    const bf16* __restrict__ ZM,
    float* __restrict__ invA, float* __restrict__ invB,
    float* __restrict__ psA, float* __restrict__ psB)
{
    __shared__ float colA[8][LEN];
    __shared__ float colB[8][LEN];
    int b = blockIdx.x, s = blockIdx.y;
    int warp = threadIdx.x >> 5, lane = threadIdx.x & 31;
    int n0 = s * (NEXP / NSPLIT);

    float ca0[4] = {}, ca1[4] = {}, cb0[4] = {}, cb1[4] = {};

    for (int r = warp; r < NEXP / NSPLIT; r += 8) {
        int n = n0 + r;
        const uint32_t* zr = reinterpret_cast<const uint32_t*>(ZM + ((size_t)b * NEXP + n) * LEN);
        float sa = 0.f, sb = 0.f;
        #pragma unroll
        for (int c = 0; c < 4; c++) {
            uint32_t u = zr[c * 32 + lane];
            float lo = bflo(u), hi = bfhi(u);
            float fa0 = fmaxf(lo, 0.f), fa1 = fmaxf(hi, 0.f);
            float fb0 = fmaxf(-lo, 0.f), fb1 = fmaxf(-hi, 0.f);
            sa += fa0 + fa1; sb += fb0 + fb1;
            ca0[c] += fa0; ca1[c] += fa1;
            cb0[c] += fb0; cb1[c] += fb1;
        }
        #pragma unroll
        for (int o = 16; o; o >>= 1) {
            sa += __shfl_down_sync(0xffffffffu, sa, o);
            sb += __shfl_down_sync(0xffffffffu, sb, o);
        }
        if (!lane) {
            invA[b * NEXP + n] = 1.f / (sa + 1e-9f);
            invB[b * NEXP + n] = 1.f / (sb + 1e-9f);
        }
    }
    #pragma unroll
    for (int c = 0; c < 4; c++) {
        colA[warp][c * 64 + 2 * lane]     = ca0[c];
        colA[warp][c * 64 + 2 * lane + 1] = ca1[c];
        colB[warp][c * 64 + 2 * lane]     = cb0[c];
        colB[warp][c * 64 + 2 * lane + 1] = cb1[c];
    }
    __syncthreads();
    int l = threadIdx.x;
    float sa = 0.f, sb = 0.f;
    #pragma unroll
    for (int w = 0; w < 8; w++) { sa += colA[w][l]; sb += colB[w][l]; }
    psA[((size_t)b * NSPLIT + s) * LEN + l] = sa;
    psB[((size_t)b * NSPLIT + s) * LEN + l] = sb;
}

__global__ void bw_final(const float* __restrict__ psA, const float* __restrict__ psB,
                         float* __restrict__ invA, float* __restrict__ invB)
{
    int b = blockIdx.x, l = threadIdx.x;
    float sa = 0.f, sb = 0.f;
    for (int s = 0; s < NSPLIT; s++) {
        sa += psA[((size_t)b * NSPLIT + s) * LEN + l];
        sb += psB[((size_t)b * NSPLIT + s) * LEN + l];
    }
    invA[b * LEN + l] = 1.f / (sa + 1e-9f);
    invB[b * LEN + l] = 1.f / (sb + 1e-9f);
}

// ------------------------- forward class GEMM (mma.sync dual, unchanged) ---------------------
__global__ void __launch_bounds__(256) classfw_bf16(
    const bf16* __restrict__ ZM,
    const bf16* __restrict__ AE, const bf16* __restrict__ BE,
    const float* __restrict__ invA, const float* __restrict__ invB,
    const int* __restrict__ nidx, const float* __restrict__ btab,
    bf16* __restrict__ CA, bf16* __restrict__ CB)
{
    __shared__ uint32_t sm[2][CF_STAGE];
    int tid = threadIdx.x;
    int b  = blockIdx.z;
    int bm = blockIdx.y * 128;
    int bn = blockIdx.x * 64;
    int warp = tid >> 5, lane = tid & 31;
    int wr = warp >> 1, wc = warp & 1;
    int g = lane >> 2, t4 = lane & 3;

    float acca[2][4][4] = {}, accb[2][4][4] = {};

    int anr = tid >> 1, alc8 = (tid & 1) * 8, alc2 = (tid & 1) * 4;
    int bl2 = tid >> 5, bdc = lane * 2;
    uint4 za; uint32_t rE0, rE1, rB0, rB1;

    auto loadregs = [&](int k0) {
        int n = bm + anr; if (n >= NEXP) n = NEXP - 1;
        za = *reinterpret_cast<const uint4*>(ZM + ((size_t)b * NEXP + n) * LEN + k0 + alc8);
        size_t e0 = ((size_t)b * LEN + k0 + 2 * bl2) * DM + bn + bdc;
        size_t e1 = e0 + DM;
        rE0 = *reinterpret_cast<const uint32_t*>(AE + e0);
        rE1 = *reinterpret_cast<const uint32_t*>(AE + e1);
        rB0 = *reinterpret_cast<const uint32_t*>(BE + e0);
        rB1 = *reinterpret_cast<const uint32_t*>(BE + e1);
    };
    auto storeregs = [&](int s) {
        uint32_t* Aa = &sm[s][0];
        uint32_t* Ab = &sm[s][CF_AB];
        uint32_t* Ba = &sm[s][2 * CF_AB];
        uint32_t* Bb = &sm[s][2 * CF_AB + CF_B];
        uint4 ua, ub;
        ua.x = bfrelu2(za.x); ub.x = bfrelu2(bfneg2(za.x));
        ua.y = bfrelu2(za.y); ub.y = bfrelu2(bfneg2(za.y));
        ua.z = bfrelu2(za.z); ub.z = bfrelu2(bfneg2(za.z));
        ua.w = bfrelu2(za.w); ub.w = bfrelu2(bfneg2(za.w));
        *reinterpret_cast<uint4*>(&Aa[anr * AFST + alc2]) = ua;
        *reinterpret_cast<uint4*>(&Ab[anr * AFST + alc2]) = ub;
        Ba[bl2 * BCST + bdc]     = __byte_perm(rE0, rE1, 0x5410);
        Ba[bl2 * BCST + bdc + 1] = __byte_perm(rE0, rE1, 0x7632);
        Bb[bl2 * BCST + bdc]     = __byte_perm(rB0, rB1, 0x5410);
        Bb[bl2 * BCST + bdc + 1] = __byte_perm(rB0, rB1, 0x7632);
    };
    auto compute = [&](int s) {
        const uint32_t* Aa = &sm[s][0];
        const uint32_t* Ab = &sm[s][CF_AB];
        const uint32_t* Ba = &sm[s][2 * CF_AB];
        const uint32_t* Bb = &sm[s][2 * CF_AB + CF_B];
        uint32_t afa[2][4], afb[2][4], bfa[4][2], bfb[4][2];
        #pragma unroll
        for (int c = 0; c < 2; c++) {
            int row = wr * 32 + c * 16 + g;
            afa[c][0] = Aa[row * AFST + t4];
            afa[c][1] = Aa[(row + 8) * AFST + t4];
            afa[c][2] = Aa[row * AFST + t4 + 4];
            afa[c][3] = Aa[(row + 8) * AFST + t4 + 4];
            afb[c][0] = Ab[row * AFST + t4];
            afb[c][1] = Ab[(row + 8) * AFST + t4];
            afb[c][2] = Ab[row * AFST + t4 + 4];
            afb[c][3] = Ab[(row + 8) * AFST + t4 + 4];
        }
        #pragma unroll
        for (int nb = 0; nb < 4; nb++) {
            int col = wc * 32 + nb * 8 + g;
            bfa[nb][0] = Ba[t4 * BCST + col];
            bfa[nb][1] = Ba[(t4 + 4) * BCST + col];
            bfb[nb][0] = Bb[t4 * BCST + col];
            bfb[nb][1] = Bb[(t4 + 4) * BCST + col];
        }
        #pragma unroll
        for (int c = 0; c < 2; c++)
            #pragma unroll
            for (int nb = 0; nb < 4; nb++) {
                mma16(acca[c][nb], afa[c], bfa[nb]);
                mma16(accb[c][nb], afb[c], bfb[nb]);
            }
    };

    loadregs(0);
    storeregs(0);
    __syncthreads();
    const int KT = LEN / 16;
    for (int t = 0; t < KT; t++) {
        if (t + 1 < KT) loadregs((t + 1) * 16);
        compute(t & 1);
        if (t + 1 < KT) storeregs((t + 1) & 1);
        __syncthreads();
    }

    #pragma unroll
    for (int c = 0; c < 2; c++) {
        #pragma unroll
        for (int h = 0; h < 2; h++) {
            int n = bm + wr * 32 + c * 16 + g + h * 8;
            if (n >= NEXP) continue;
            float ia = invA[b * NEXP + n];
            float ib = invB[b * NEXP + n];
            int qi = nidx[b * NEXP + n];
            #pragma unroll
            for (int nb = 0; nb < 4; nb++) {
                int d0 = bn + wc * 32 + nb * 8 + 2 * t4;
                float2 bi = *reinterpret_cast<const float2*>(btab + (size_t)qi * DM + d0);
                size_t off = ((size_t)b * NEXP + n) * DM + d0;
                *reinterpret_cast<uint32_t*>(CA + off) =
                    f2bf2(acca[c][nb][h * 2 + 0] * ia + bi.x,
                          acca[c][nb][h * 2 + 1] * ia + bi.y);
                *reinterpret_cast<uint32_t*>(CB + off) =
                    f2bf2(accb[c][nb][h * 2 + 0] * ib + bi.x,
                          accb[c][nb][h * 2 + 1] * ib + bi.y);
            }
        }
    }
}

// ------------------------- backward class GEMM (mma.sync dual, unchanged) --------------------
__global__ void __launch_bounds__(256) classbw_bf16(
    const bf16* __restrict__ ZM,
    const bf16* __restrict__ CA, const bf16* __restrict__ CB,
    const float* __restrict__ invA, const float* __restrict__ invB,
    const float* __restrict__ SELp, const float* __restrict__ X,
    float* __restrict__ X1)
{
    __shared__ uint32_t sm[2][CB_STAGE];
    int tid = threadIdx.x;
    int b  = blockIdx.z;
    int bl = blockIdx.y * 128;
    int bn = blockIdx.x * 64;
    int warp = tid >> 5, lane = tid & 31;
    int wr = warp >> 1, wc = warp & 1;
    int g = lane >> 2, t4 = lane & 3;

    float acca[2][4][4] = {}, accb[2][4][4] = {};

    int n2 = tid >> 5, l4 = lane * 4;
    int bdc = lane * 2;
    uint2 ze, zo; uint32_t rC0, rC1, rD0, rD1;

    auto loadregs = [&](int k0) {
        size_t z0 = ((size_t)b * NEXP + k0 + 2 * n2) * LEN + bl + l4;
        ze = *reinterpret_cast<const uint2*>(ZM + z0);
        zo = *reinterpret_cast<const uint2*>(ZM + z0 + LEN);
        size_t c0 = ((size_t)b * NEXP + k0 + 2 * n2) * DM + bn + bdc;
        size_t c1 = c0 + DM;
        rC0 = *reinterpret_cast<const uint32_t*>(CA + c0);
        rC1 = *reinterpret_cast<const uint32_t*>(CA + c1);
        rD0 = *reinterpret_cast<const uint32_t*>(CB + c0);
        rD1 = *reinterpret_cast<const uint32_t*>(CB + c1);
    };
    auto storeregs = [&](int s) {
        uint32_t* Aa = &sm[s][0];
        uint32_t* Ab = &sm[s][CB_AB];
        uint32_t* Ba = &sm[s][2 * CB_AB];
        uint32_t* Bb = &sm[s][2 * CB_AB + CF_B];
        uint32_t p[4];
        p[0] = __byte_perm(ze.x, zo.x, 0x5410);
        p[1] = __byte_perm(ze.x, zo.x, 0x7632);
        p[2] = __byte_perm(ze.y, zo.y, 0x5410);
        p[3] = __byte_perm(ze.y, zo.y, 0x7632);
        #pragma unroll
        for (int i = 0; i < 4; i++) {
            Aa[(l4 + i) * ABST + n2] = bfrelu2(p[i]);
            Ab[(l4 + i) * ABST + n2] = bfrelu2(bfneg2(p[i]));
        }
        Ba[n2 * BCST + bdc]     = __byte_perm(rC0, rC1, 0x5410);
        Ba[n2 * BCST + bdc + 1] = __byte_perm(rC0, rC1, 0x7632);
        Bb[n2 * BCST + bdc]     = __byte_perm(rD0, rD1, 0x5410);
        Bb[n2 * BCST + bdc + 1] = __byte_perm(rD0, rD1, 0x7632);
    };
    auto compute = [&](int s) {
        const uint32_t* Aa = &sm[s][0];
        const uint32_t* Ab = &sm[s][CB_AB];
        const uint32_t* Ba = &sm[s][2 * CB_AB];
        const uint32_t* Bb = &sm[s][2 * CB_AB + CF_B];
        uint32_t afa[2][4], afb[2][4], bfa[4][2], bfb[4][2];
        #pragma unroll
        for (int c = 0; c < 2; c++) {
            int row = wr * 32 + c * 16 + g;
            afa[c][0] = Aa[row * ABST + t4];
            afa[c][1] = Aa[(row + 8) * ABST + t4];
            afa[c][2] = Aa[row * ABST + t4 + 4];
            afa[c][3] = Aa[(row + 8) * ABST + t4 + 4];
            afb[c][0] = Ab[row * ABST + t4];
            afb[c][1] = Ab[(row + 8) * ABST + t4];
            afb[c][2] = Ab[row * ABST + t4 + 4];
            afb[c][3] = Ab[(row + 8) * ABST + t4 + 4];
        }
        #pragma unroll
        for (int nb = 0; nb < 4; nb++) {
            int col = wc * 32 + nb * 8 + g;
            bfa[nb][0] = Ba[t4 * BCST + col];
            bfa[nb][1] = Ba[(t4 + 4) * BCST + col];
            bfb[nb][0] = Bb[t4 * BCST + col];
            bfb[nb][1] = Bb[(t4 + 4) * BCST + col];
        }
        #pragma unroll
        for (int c = 0; c < 2; c++)
            #pragma unroll
            for (int nb = 0; nb < 4; nb++) {
                mma16(acca[c][nb], afa[c], bfa[nb]);
                mma16(accb[c][nb], afb[c], bfb[nb]);
            }
    };

    loadregs(0);
    storeregs(0);
    __syncthreads();
    const int KT = NEXP / 16;
    for (int t = 0; t < KT; t++) {
        if (t + 1 < KT) loadregs((t + 1) * 16);
        compute(t & 1);
        if (t + 1 < KT) storeregs((t + 1) & 1);
        __syncthreads();
    }

    #pragma unroll
    for (int c = 0; c < 2; c++) {
        #pragma unroll
        for (int h = 0; h < 2; h++) {
            int l = bl + wr * 32 + c * 16 + g + h * 8;
            float ia = invA[b * LEN + l];
            float ib = invB[b * LEN + l];
            #pragma unroll
            for (int nb = 0; nb < 4; nb++) {
                int d0 = bn + wc * 32 + nb * 8 + 2 * t4;
                size_t off = ((size_t)b * LEN + l) * DM + d0;
                float2 s2 = *reinterpret_cast<const float2*>(SELp + off);
                float2 x2 = *reinterpret_cast<const float2*>(X + off);
                float2 o;
                o.x = x2.x + s2.x * (acca[c][nb][h * 2 + 0] * ia)
                           + (1.f - s2.x) * (accb[c][nb][h * 2 + 0] * ib);
                o.y = x2.y + s2.y * (acca[c][nb][h * 2 + 1] * ia)
                           + (1.f - s2.y) * (accb[c][nb][h * 2 + 1] * ib);
                *reinterpret_cast<float2*>(X1 + off) = o;
            }
        }
    }
}

// ------------------------- launch -------------------------
extern "C" void kernel_launch(void* const* d_in, const int* in_sizes, int n_in,
                              void* d_out, int out_size)
{
    const float* x     = (const float*)d_in[0];
    const int*   nidx  = (const int*)d_in[1];
    const int*   mask  = (const int*)d_in[2];
    const float* ln1_g = (const float*)d_in[3];
    const float* ln1_b = (const float*)d_in[4];
    const float* ln2_g = (const float*)d_in[5];
    const float* ln2_b = (const float*)d_in[6];
    const float* q_tab = (const float*)d_in[7];
    const float* b_tab = (const float*)d_in[8];
    const float* Wk  = (const float*)d_in[9];  const float* bk   = (const float*)d_in[10];
    const float* Wa  = (const float*)d_in[11]; const float* ba   = (const float*)d_in[12];
    const float* Wa1 = (const float*)d_in[13]; const float* ba1  = (const float*)d_in[14];
    const float* Wb  = (const float*)d_in[15]; const float* bb   = (const float*)d_in[16];
    const float* Wb1 = (const float*)d_in[17]; const float* bb1  = (const float*)d_in[18];
    const float* Ws  = (const float*)d_in[19]; const float* bsel = (const float*)d_in[20];
    const float* Wf1 = (const float*)d_in[21]; const float* bf1  = (const float*)d_in[22];
    const float* Wf2 = (const float*)d_in[23]; const float* bf2  = (const float*)d_in[24];
    float* out = (float*)d_out;

    bf16 *pX2, *pXK, *pEA0, *pEB0, *pAE, *pBE, *pZM, *pCA, *pCB, *pH, *pWH, *pQH;
    float *pSEL, *pX1, *pIAf, *pIBf, *pPA, *pPB, *pIAb, *pIBb;
    cudaGetSymbolAddress((void**)&pX2, g_X2);
    cudaGetSymbolAddress((void**)&pXK, g_XK);
    cudaGetSymbolAddress((void**)&pEA0, g_EA0);
    cudaGetSymbolAddress((void**)&pEB0, g_EB0);
    cudaGetSymbolAddress((void**)&pAE, g_AE);
    cudaGetSymbolAddress((void**)&pBE, g_BE);
    cudaGetSymbolAddress((void**)&pSEL, g_SEL);
    cudaGetSymbolAddress((void**)&pX1, g_X1);
    cudaGetSymbolAddress((void**)&pZM, g_ZM);
    cudaGetSymbolAddress((void**)&pCA, g_CA);
    cudaGetSymbolAddress((void**)&pCB, g_CB);
    cudaGetSymbolAddress((void**)&pH, g_H);
    cudaGetSymbolAddress((void**)&pIAf, g_IAf);
    cudaGetSymbolAddress((void**)&pIBf, g_IBf);
    cudaGetSymbolAddress((void**)&pPA, g_PA);
    cudaGetSymbolAddress((void**)&pPB, g_PB);
    cudaGetSymbolAddress((void**)&pIAb, g_IAb);
    cudaGetSymbolAddress((void**)&pIBb, g_IBb);
    cudaGetSymbolAddress((void**)&pWH, g_WH);
    cudaGetSymbolAddress((void**)&pQH, g_QH);

    bf16* WkH  = pWH;                  // [512,512] (K,N)
    bf16* WaH  = pWH + 262144;
    bf16* WbH  = pWH + 524288;
    bf16* WsH  = pWH + 786432;
    bf16* Wa1H = pWH + 1048576;
    bf16* Wb1H = pWH + 1310720;
    bf16* Wf1H = pWH + 1572864;        // [512,2048]
    bf16* Wf2H = pWH + 2621440;        // [2048,512]

    // 0. fused weight conversion (1 launch)
    CvtArgs ca;
    ca.s[0] = Wk;  ca.d[0] = WkH;
    ca.s[1] = Wa;  ca.d[1] = WaH;
    ca.s[2] = Wb;  ca.d[2] = WbH;
    ca.s[3] = Ws;  ca.d[3] = WsH;
    ca.s[4] = Wa1; ca.d[4] = Wa1H;
    ca.s[5] = Wb1; ca.d[5] = Wb1H;
    ca.s[6] = Wf1; ca.d[6] = Wf1H;
    ca.s[7] = Wf2; ca.d[7] = Wf2H;
    ca.s[8] = q_tab; ca.d[8] = pQH;
    int sizes4[9] = {65536, 65536, 65536, 65536, 65536, 65536, 262144, 262144, 126976};
    ca.cum[0] = 0;
    for (int i = 0; i < 9; i++) ca.cum[i + 1] = ca.cum[i] + sizes4[i];
    cvt_all<<<(ca.cum[9] + 255) / 256, 256>>>(ca);

    // 1. LN1
    ln_kernel<<<M1, 128>>>(x, ln1_g, ln1_b, pX2);

    // 2. merged dense projections: {Wk, Wa, Wb, Ws} in one launch
    GArg gk = {pX2, WkH, bk,   nullptr, pXK,  0};
    GArg ga_ = {pX2, WaH, ba,  nullptr, pEA0, 0};
    GArg gb = {pX2, WbH, bb,   nullptr, pEB0, 0};
    GArg gs = {pX2, WsH, bsel, nullptr, pSEL, 1};
    gemm_multi<<<dim3(DM / 128, M1 / 128, 4), 256>>>(gk, ga_, gb, gs, M1, DM, DM);

    // 3. z GEMM
    zgemm_bf16<<<dim3(LEN / 128, (NEXP + 127) / 128, BSZ), 256>>>(nidx, pQH, pXK, mask, pZM);

    // 4. merged gated projections: {Wa1, Wb1}
    GArg g1 = {pEA0, Wa1H, ba1, pEA0, pAE, 3};
    GArg g2 = {pEB0, Wb1H, bb1, pEB0, pBE, 3};
    gemm_multi<<<dim3(DM / 128, M1 / 128, 2), 256>>>(g1, g2, g1, g1, M1, DM, DM);

    // 5. sums
    sums_fused<<<dim3(BSZ, NSPLIT), 256>>>(pZM, pIAf, pIBf, pPA, pPB);
    bw_final<<<BSZ, LEN>>>(pPA, pPB, pIAb, pIBb);

    // 6. class GEMMs
    classfw_bf16<<<dim3(DM / 64, (NEXP + 127) / 128, BSZ), 256>>>(
        pZM, pAE, pBE, pIAf, pIBf, nidx, b_tab, pCA, pCB);
    classbw_bf16<<<dim3(DM / 64, LEN / 128, BSZ), 256>>>(
        pZM, pCA, pCB, pIAb, pIBb, pSEL, x, pX1);

    // 7. LN2 + FFN
    ln_kernel<<<M1, 128>>>(pX1, ln2_g, ln2_b, pX2);
    GArg gf1 = {pX2, Wf1H, bf1, nullptr, pH, 2};
    gemm_multi<<<dim3(DFF / 128, M1 / 128, 1), 256>>>(gf1, gf1, gf1, gf1, M1, DFF, DM);
    GArg gf2 = {pH, Wf2H, bf2, pX1, out, 4};
    gemm_multi<<<dim3(DM / 128, M1 / 128, 1), 256>>>(gf2, gf2, gf2, gf2, M1, DM, DFF);
}